// round 1
// baseline (speedup 1.0000x reference)
#include <cuda_runtime.h>
#include <math.h>

// ---------------- scratch (__device__ globals; no allocs allowed) ----------------
__device__ float g_col[254476800];   // max im2col: ct4 = 220900 x 1152
__device__ float g_wT[13107200];     // max weight transform: fc_w^T = 800 x 16384
__device__ float g_h1[13107200];     // 100x128x32x32
__device__ float g_h2[6553600];      // 100x256x16x16
__device__ float g_h3[6553600];      // 100x1024x8x8
__device__ float g_h4[1638400];      // 100x1024x4x4
__device__ float g_R[80000];         // 100x800  (= Y = fft2(sig).real)
__device__ float g_tab[800];
__device__ float g_mean[1024];
__device__ float g_invstd[1024];
__device__ float g_d0[921600];       // 100x1024x3x3
__device__ float g_t1[1280000];      // 100x512x5x5
__device__ float g_t2[3097600];      // 100x256x11x11
__device__ float g_t3[6771200];      // 100x128x23x23
__device__ float g_t4[14137600];     // 100x64x47x47

// ---------------- kernels ----------------

__global__ void fill_costab(float* tab) {
    int k = blockIdx.x * blockDim.x + threadIdx.x;
    if (k < 800) tab[k] = (float)cos(2.0 * 3.141592653589793238462643 * (double)k / 800.0);
}

// forward-conv im2col, optional fused batchnorm on the input
// grid: (B*OH*OW, ceil(CI*9/256)), block 256
__global__ void im2colF(const float* __restrict__ in, const float* __restrict__ mean,
                        const float* __restrict__ invstd, float* __restrict__ col,
                        int CI, int IH, int IW, int OH, int OW, int s, int p) {
    int row = blockIdx.x;
    int kk  = blockIdx.y * blockDim.x + threadIdx.x;
    int K = CI * 9;
    if (kk >= K) return;
    int OHW = OH * OW;
    int b = row / OHW, hw = row % OHW;
    int oy = hw / OW, ox = hw % OW;
    int ci = kk / 9, r = kk % 9, ky = r / 3, kx = r % 3;
    int iy = oy * s - p + ky, ix = ox * s - p + kx;
    float v = 0.f;
    if (iy >= 0 && iy < IH && ix >= 0 && ix < IW) {
        v = in[(((long long)b * CI + ci) * IH + iy) * IW + ix];
        if (mean) v = (v - mean[ci]) * invstd[ci];
    }
    col[(long long)row * K + kk] = v;
}

// transposed-conv im2col (conv over stride-dilated input, pad p = 2 - pad_orig)
__global__ void im2colT(const float* __restrict__ in, float* __restrict__ col,
                        int CI, int IH, int IW, int OH, int OW, int s, int p) {
    int row = blockIdx.x;
    int kk  = blockIdx.y * blockDim.x + threadIdx.x;
    int K = CI * 9;
    if (kk >= K) return;
    int OHW = OH * OW;
    int b = row / OHW, hw = row % OHW;
    int oy = hw / OW, ox = hw % OW;
    int ci = kk / 9, r = kk % 9, ky = r / 3, kx = r % 3;
    int ty = oy + ky - p, tx = ox + kx - p;
    float v = 0.f;
    int dh = s * (IH - 1), dw = s * (IW - 1);
    if (ty >= 0 && ty <= dh && tx >= 0 && tx <= dw && (ty % s) == 0 && (tx % s) == 0) {
        v = in[(((long long)b * CI + ci) * IH + ty / s) * IW + tx / s];
    }
    col[(long long)row * K + kk] = v;
}

// C[M,N] = A[M,K] @ B[N,K]^T, epilogue: bias + {0:none,1:leaky,2:relu}
// output scattered to NCHW: row = b*HW + hw, col = channel
#define BM 64
#define BN 64
#define BKK 16
__global__ void gemm_kernel(const float* __restrict__ A, const float* __restrict__ Bm,
                            const float* __restrict__ bias, float* __restrict__ C,
                            int M, int N, int K, int HW, int CO, int epil) {
    __shared__ float As[BKK][BM + 1];
    __shared__ float Bs[BKK][BN + 1];
    int m0 = blockIdx.y * BM, n0 = blockIdx.x * BN;
    int t = threadIdx.x;
    int tx = t & 15, ty = t >> 4;
    float acc[4][4] = {};
    for (int k0 = 0; k0 < K; k0 += BKK) {
#pragma unroll
        for (int i = 0; i < 4; i++) {
            int idx = t + i * 256;
            int r = idx >> 4, c = idx & 15;
            int gm = m0 + r, gk = k0 + c;
            As[c][r] = (gm < M && gk < K) ? A[(long long)gm * K + gk] : 0.f;
        }
#pragma unroll
        for (int i = 0; i < 4; i++) {
            int idx = t + i * 256;
            int r = idx >> 4, c = idx & 15;
            int gn = n0 + r, gk = k0 + c;
            Bs[c][r] = (gn < N && gk < K) ? Bm[(long long)gn * K + gk] : 0.f;
        }
        __syncthreads();
#pragma unroll
        for (int k = 0; k < BKK; k++) {
            float a[4], b[4];
#pragma unroll
            for (int i = 0; i < 4; i++) a[i] = As[k][ty * 4 + i];
#pragma unroll
            for (int j = 0; j < 4; j++) b[j] = Bs[k][tx * 4 + j];
#pragma unroll
            for (int i = 0; i < 4; i++)
#pragma unroll
                for (int j = 0; j < 4; j++) acc[i][j] += a[i] * b[j];
        }
        __syncthreads();
    }
#pragma unroll
    for (int i = 0; i < 4; i++) {
        int gm = m0 + ty * 4 + i;
        if (gm >= M) continue;
        int b = gm / HW, hw = gm % HW;
#pragma unroll
        for (int j = 0; j < 4; j++) {
            int gn = n0 + tx * 4 + j;
            if (gn >= N) continue;
            float v = acc[i][j] + bias[gn];
            if (epil == 1) v = (v >= 0.f) ? v : 0.01f * v;
            else if (epil == 2) v = fmaxf(v, 0.f);
            C[((long long)b * CO + gn) * HW + hw] = v;
        }
    }
}

// per-channel mean/invstd over (B, H, W); one block per channel
__global__ void bn_stats(const float* __restrict__ h, float* mean, float* invstd,
                         int C, int Bn, int HW) {
    int c = blockIdx.x;
    float s = 0.f, ss = 0.f;
    for (int b = 0; b < Bn; b++) {
        const float* p = h + ((long long)b * C + c) * HW;
        for (int i = threadIdx.x; i < HW; i += 256) {
            float v = p[i];
            s += v; ss += v * v;
        }
    }
    __shared__ float rs[256], rss[256];
    rs[threadIdx.x] = s; rss[threadIdx.x] = ss;
    __syncthreads();
    for (int st = 128; st > 0; st >>= 1) {
        if (threadIdx.x < st) { rs[threadIdx.x] += rs[threadIdx.x + st]; rss[threadIdx.x] += rss[threadIdx.x + st]; }
        __syncthreads();
    }
    if (threadIdx.x == 0) {
        float cnt = (float)Bn * (float)HW;
        float m = rs[0] / cnt;
        float var = rss[0] / cnt - m * m;
        mean[c] = m;
        invstd[c] = rsqrtf(var + 1e-5f);
    }
}

__global__ void norm_inplace(float* h, const float* __restrict__ mean,
                             const float* __restrict__ invstd, int C, int HW, int total) {
    int idx = blockIdx.x * blockDim.x + threadIdx.x;
    if (idx >= total) return;
    int c = (idx / HW) % C;
    h[idx] = (h[idx] - mean[c]) * invstd[c];
}

// dst[N,K] = src[K,N]^T  (tiled)
__global__ void transpose_kn(const float* __restrict__ src, float* __restrict__ dst, int K, int N) {
    __shared__ float tile[32][33];
    int k0 = blockIdx.y * 32, n0 = blockIdx.x * 32;
    int tx = threadIdx.x, ty = threadIdx.y;
    for (int i = 0; i < 32; i += 8) {
        int k = k0 + ty + i, n = n0 + tx;
        if (k < K && n < N) tile[ty + i][tx] = src[(long long)k * N + n];
    }
    __syncthreads();
    for (int i = 0; i < 32; i += 8) {
        int n = n0 + ty + i, k = k0 + tx;
        if (n < N && k < K) dst[(long long)n * K + k] = tile[tx][ty + i];
    }
}

// convT weight: wt[co][ci*9+ky*3+kx] = w[ci][co][2-ky][2-kx], w shape (CI, CO, 3, 3)
__global__ void wt_convT(const float* __restrict__ w, float* __restrict__ wt, int CI, int CO) {
    int idx = blockIdx.x * blockDim.x + threadIdx.x;
    int total = CO * CI * 9;
    if (idx >= total) return;
    int co = idx / (CI * 9);
    int r = idx % (CI * 9);
    int ci = r / 9, rr = r % 9, ky = rr / 3, kx = rr % 3;
    wt[idx] = w[(((long long)ci * CO + co) * 3 + (2 - ky)) * 3 + (2 - kx)];
}

// R[b, m*8+l] = sum_{m',l'} eig[b, m'*8+l'] * cos(2pi*(m*m'/100 + l*l'/8))
__global__ void compute_R(const float* __restrict__ eig, const float* __restrict__ tab,
                          float* __restrict__ R) {
    int b = blockIdx.x;
    __shared__ float s[800];
    __shared__ float t[800];
    for (int i = threadIdx.x; i < 800; i += 256) { s[i] = eig[b * 800 + i]; t[i] = tab[i]; }
    __syncthreads();
    for (int o = threadIdx.x; o < 800; o += 256) {
        int m = o >> 3, l = o & 7;
        float acc = 0.f;
        for (int q = 0; q < 800; q++) {
            int mp = q >> 3, lp = q & 7;
            int ph = (8 * m * mp + 100 * l * lp) % 800;
            acc += s[q] * t[ph];
        }
        R[b * 800 + o] = acc;
    }
}

// C[b,i,j] = (R[b, (i-j) mod 800]) / sqrt(800);  grid (800, 100)
__global__ void write_C(const float* __restrict__ R, float* __restrict__ C) {
    int b = blockIdx.y;
    int i = blockIdx.x;
    __shared__ float r[800];
    const float inv = 0.035355339059327376f; // 1/sqrt(800)
    for (int q = threadIdx.x; q < 800; q += 256) r[q] = R[b * 800 + q] * inv;
    __syncthreads();
    long long base = ((long long)b * 800 + i) * 800;
    for (int j = threadIdx.x; j < 800; j += 256)
        C[base + j] = r[(i - j + 800) % 800];
}

// ---------------- host side ----------------

static float* symaddr(const void* s) {
    void* p = nullptr;
    cudaGetSymbolAddress(&p, s);
    return (float*)p;
}

static void gemm(const float* A, const float* Bm, const float* bias, float* C,
                 int M, int N, int K, int HW, int CO, int epil) {
    dim3 g((N + BN - 1) / BN, (M + BM - 1) / BM);
    gemm_kernel<<<g, 256>>>(A, Bm, bias, C, M, N, K, HW, CO, epil);
}

static void run_im2colF(const float* in, const float* mean, const float* invstd, float* col,
                        int B, int CI, int IH, int IW, int OH, int OW, int s, int p) {
    dim3 g(B * OH * OW, (CI * 9 + 255) / 256);
    im2colF<<<g, 256>>>(in, mean, invstd, col, CI, IH, IW, OH, OW, s, p);
}

static void run_im2colT(const float* in, float* col,
                        int B, int CI, int IH, int IW, int OH, int OW, int s, int p) {
    dim3 g(B * OH * OW, (CI * 9 + 255) / 256);
    im2colT<<<g, 256>>>(in, col, CI, IH, IW, OH, OW, s, p);
}

extern "C" void kernel_launch(void* const* d_in, const int* in_sizes, int n_in,
                              void* d_out, int out_size) {
    const float* x       = (const float*)d_in[0];
    const float* conv1_w = (const float*)d_in[1];
    const float* conv1_b = (const float*)d_in[2];
    const float* conv2_w = (const float*)d_in[3];
    const float* conv2_b = (const float*)d_in[4];
    const float* conv3_w = (const float*)d_in[5];
    const float* conv3_b = (const float*)d_in[6];
    const float* conv4_w = (const float*)d_in[7];
    const float* conv4_b = (const float*)d_in[8];
    const float* fc_w    = (const float*)d_in[9];
    const float* fc_b    = (const float*)d_in[10];
    const float* dec_w   = (const float*)d_in[11];
    const float* dec_b   = (const float*)d_in[12];
    const float* ct1_w   = (const float*)d_in[13];
    const float* ct1_b   = (const float*)d_in[14];
    const float* ct2_w   = (const float*)d_in[15];
    const float* ct2_b   = (const float*)d_in[16];
    const float* ct3_w   = (const float*)d_in[17];
    const float* ct3_b   = (const float*)d_in[18];
    const float* ct4_w   = (const float*)d_in[19];
    const float* ct4_b   = (const float*)d_in[20];
    const float* ct5_w   = (const float*)d_in[21];
    const float* ct5_b   = (const float*)d_in[22];

    float* out = (float*)d_out;
    // output layout: d (100*49*49) | C (100*800*800) | eig (100*800)
    float* out_d   = out;
    float* out_C   = out + 240100;
    float* out_eig = out + 240100 + 64000000;

    float* col  = symaddr(g_col);
    float* wT   = symaddr(g_wT);
    float* h1   = symaddr(g_h1);
    float* h2   = symaddr(g_h2);
    float* h3   = symaddr(g_h3);
    float* h4   = symaddr(g_h4);
    float* R    = symaddr(g_R);
    float* tab  = symaddr(g_tab);
    float* mean = symaddr(g_mean);
    float* ivs  = symaddr(g_invstd);
    float* d0   = symaddr(g_d0);
    float* t1   = symaddr(g_t1);
    float* t2   = symaddr(g_t2);
    float* t3   = symaddr(g_t3);
    float* t4   = symaddr(g_t4);

    const int B = 100;

    fill_costab<<<4, 256>>>(tab);

    // ---- encoder ----
    // conv1: 1 -> 128, 64 -> 32
    run_im2colF(x, nullptr, nullptr, col, B, 1, 64, 64, 32, 32, 2, 1);
    gemm(col, conv1_w, conv1_b, h1, B * 32 * 32, 128, 9, 32 * 32, 128, 1);
    bn_stats<<<128, 256>>>(h1, mean, ivs, 128, B, 32 * 32);

    // conv2: 128 -> 256, 32 -> 16 (BN of h1 fused into im2col)
    run_im2colF(h1, mean, ivs, col, B, 128, 32, 32, 16, 16, 2, 1);
    gemm(col, conv2_w, conv2_b, h2, B * 16 * 16, 256, 128 * 9, 16 * 16, 256, 1);
    bn_stats<<<256, 256>>>(h2, mean, ivs, 256, B, 16 * 16);

    // conv3: 256 -> 1024, 16 -> 8
    run_im2colF(h2, mean, ivs, col, B, 256, 16, 16, 8, 8, 2, 1);
    gemm(col, conv3_w, conv3_b, h3, B * 8 * 8, 1024, 256 * 9, 8 * 8, 1024, 1);
    bn_stats<<<1024, 256>>>(h3, mean, ivs, 1024, B, 8 * 8);

    // conv4: 1024 -> 1024, 8 -> 4
    run_im2colF(h3, mean, ivs, col, B, 1024, 8, 8, 4, 4, 2, 1);
    gemm(col, conv4_w, conv4_b, h4, B * 4 * 4, 1024, 1024 * 9, 4 * 4, 1024, 1);
    bn_stats<<<1024, 256>>>(h4, mean, ivs, 1024, B, 4 * 4);
    norm_inplace<<<(1638400 + 255) / 256, 256>>>(h4, mean, ivs, 1024, 16, 1638400);

    // fc: (100,16384) @ (16384,800) + relu -> eig (written straight into output)
    {
        dim3 g((800 + 31) / 32, (16384 + 31) / 32);
        transpose_kn<<<g, dim3(32, 8)>>>(fc_w, wT, 16384, 800);
    }
    gemm(h4, wT, fc_b, out_eig, B, 800, 16384, 1, 800, 2);

    // ---- spectral part ----
    compute_R<<<B, 256>>>(out_eig, tab, R);
    write_C<<<dim3(800, B), 256>>>(R, out_C);

    // dec: (100,800) @ (800,9216) -> d0 (100,1024,3,3)
    {
        dim3 g((9216 + 31) / 32, (800 + 31) / 32);
        transpose_kn<<<g, dim3(32, 8)>>>(dec_w, wT, 800, 9216);
    }
    gemm(R, wT, dec_b, d0, B, 9216, 800, 1, 9216, 0);

    // ---- decoder (transposed convs via dilated-conv im2col) ----
    // ct1: 1024 -> 512, 3 -> 5, s2, pad_orig 1 -> p=1
    wt_convT<<<(512 * 1024 * 9 + 255) / 256, 256>>>(ct1_w, wT, 1024, 512);
    run_im2colT(d0, col, B, 1024, 3, 3, 5, 5, 2, 1);
    gemm(col, wT, ct1_b, t1, B * 25, 512, 1024 * 9, 25, 512, 0);

    // ct2: 512 -> 256, 5 -> 11, s2, p=2
    wt_convT<<<(256 * 512 * 9 + 255) / 256, 256>>>(ct2_w, wT, 512, 256);
    run_im2colT(t1, col, B, 512, 5, 5, 11, 11, 2, 2);
    gemm(col, wT, ct2_b, t2, B * 121, 256, 512 * 9, 121, 256, 0);

    // ct3: 256 -> 128, 11 -> 23, s2, p=2
    wt_convT<<<(128 * 256 * 9 + 255) / 256, 256>>>(ct3_w, wT, 256, 128);
    run_im2colT(t2, col, B, 256, 11, 11, 23, 23, 2, 2);
    gemm(col, wT, ct3_b, t3, B * 529, 128, 256 * 9, 529, 128, 0);

    // ct4: 128 -> 64, 23 -> 47, s2, p=2
    wt_convT<<<(64 * 128 * 9 + 255) / 256, 256>>>(ct4_w, wT, 128, 64);
    run_im2colT(t3, col, B, 128, 23, 23, 47, 47, 2, 2);
    gemm(col, wT, ct4_b, t4, B * 2209, 64, 128 * 9, 2209, 64, 0);

    // ct5: 64 -> 1, 47 -> 49, s1, p=2
    wt_convT<<<(1 * 64 * 9 + 255) / 256, 256>>>(ct5_w, wT, 64, 1);
    run_im2colT(t4, col, B, 64, 47, 47, 49, 49, 1, 2);
    gemm(col, wT, ct5_b, out_d, B * 2401, 1, 64 * 9, 2401, 1, 0);
}

// round 2
// speedup vs baseline: 2.7837x; 2.7837x over previous
#include <cuda_runtime.h>
#include <math.h>

// ---------------- scratch (__device__ globals; no allocs allowed) ----------------
__device__ float g_col[29600000];   // max im2col: conv2 / ct4(e,e) = 29.49M floats
__device__ float g_wT[13200000];    // max: fc_w^T = 800 x 16384
__device__ float g_h1[13107200];    // 100x128x32x32
__device__ float g_h2[6553600];     // 100x256x16x16
__device__ float g_h3[6553600];     // 100x1024x8x8
__device__ float g_h4[1638400];     // 100x1024x4x4
__device__ float g_R[80000];        // 100x800
__device__ float g_tab[800];
__device__ float g_mean[1024];
__device__ float g_invstd[1024];
__device__ float g_bnsum[1024];
__device__ float g_bnss[1024];
__device__ float g_d0[921600];      // 100x1024x3x3
__device__ float g_t1[1280000];     // 100x512x5x5
__device__ float g_t2[3097600];     // 100x256x11x11
__device__ float g_t3[6771200];     // 100x128x23x23
__device__ float g_t4[14137600];    // 100x64x47x47

// ---------------- GEMM: C = A[M,K] @ B[N,K]^T, double-buffered ----------------
// epil: 0 none, 1 leaky, 2 relu, 3 raw split-K partial (C[(z*M+gm)*N+gn])
// scatter: b = gm/HWp, hw = (py + sy*(lhw/OWp))*OWfull + (px + sx*(lhw%OWp))
template<int BM, int BN, int TM, int TN>
__global__ void __launch_bounds__(256, 2)
gemm_t(const float* __restrict__ A, const float* __restrict__ Bm,
       const float* __restrict__ bias, float* __restrict__ C,
       int M, int N, int K, int lda, int ldb,
       int CO, int HWp, int HWfull, int OWp, int OWfull,
       int sy, int sx, int py, int px, int epil)
{
    constexpr int BK = 16;
    constexpr int NVA = (BM * BK) / (4 * 256);
    constexpr int NVB = (BN * BK) / (4 * 256);
    __shared__ __align__(16) float As[2][BK][BM + 4];
    __shared__ __align__(16) float Bs[2][BK][BN + 4];
    const int tid = threadIdx.x;
    const int tx = tid & 15;    // M direction (fine)
    const int ty = tid >> 4;    // N direction
    const int m0 = blockIdx.y * BM;
    const int n0 = blockIdx.x * BN;
    const int koff = blockIdx.z * K;
    const bool vecOK = ((K & 15) == 0) && ((lda & 3) == 0) && ((ldb & 3) == 0);
    const int NT = (K + BK - 1) / BK;

    float acc[TM][TN];
#pragma unroll
    for (int i = 0; i < TM; i++)
#pragma unroll
        for (int j = 0; j < TN; j++) acc[i][j] = 0.f;

    float4 ra[NVA], rb[NVB];

    auto load_tiles = [&](int t) {
        const int k0 = koff + t * BK;
        if (vecOK) {
#pragma unroll
            for (int i = 0; i < NVA; i++) {
                int vid = tid + i * 256;
                int r = vid >> 2, kc = (vid & 3) << 2;
                int gm = m0 + r;
                ra[i] = (gm < M) ? *(const float4*)(A + (size_t)gm * lda + k0 + kc)
                                 : make_float4(0.f, 0.f, 0.f, 0.f);
            }
#pragma unroll
            for (int i = 0; i < NVB; i++) {
                int vid = tid + i * 256;
                int r = vid >> 2, kc = (vid & 3) << 2;
                int gn = n0 + r;
                rb[i] = (gn < N) ? *(const float4*)(Bm + (size_t)gn * ldb + k0 + kc)
                                 : make_float4(0.f, 0.f, 0.f, 0.f);
            }
        } else {
            const int kend = koff + K;
#pragma unroll
            for (int i = 0; i < NVA; i++) {
                int vid = tid + i * 256;
                int r = vid >> 2, kc = (vid & 3) << 2;
                int gm = m0 + r;
                float v[4];
#pragma unroll
                for (int j = 0; j < 4; j++) {
                    int gk = k0 + kc + j;
                    v[j] = (gm < M && gk < kend) ? A[(size_t)gm * lda + gk] : 0.f;
                }
                ra[i] = make_float4(v[0], v[1], v[2], v[3]);
            }
#pragma unroll
            for (int i = 0; i < NVB; i++) {
                int vid = tid + i * 256;
                int r = vid >> 2, kc = (vid & 3) << 2;
                int gn = n0 + r;
                float v[4];
#pragma unroll
                for (int j = 0; j < 4; j++) {
                    int gk = k0 + kc + j;
                    v[j] = (gn < N && gk < kend) ? Bm[(size_t)gn * ldb + gk] : 0.f;
                }
                rb[i] = make_float4(v[0], v[1], v[2], v[3]);
            }
        }
    };
    auto store_tiles = [&](int buf) {
#pragma unroll
        for (int i = 0; i < NVA; i++) {
            int vid = tid + i * 256;
            int r = vid >> 2, kc = (vid & 3) << 2;
            As[buf][kc + 0][r] = ra[i].x;
            As[buf][kc + 1][r] = ra[i].y;
            As[buf][kc + 2][r] = ra[i].z;
            As[buf][kc + 3][r] = ra[i].w;
        }
#pragma unroll
        for (int i = 0; i < NVB; i++) {
            int vid = tid + i * 256;
            int r = vid >> 2, kc = (vid & 3) << 2;
            Bs[buf][kc + 0][r] = rb[i].x;
            Bs[buf][kc + 1][r] = rb[i].y;
            Bs[buf][kc + 2][r] = rb[i].z;
            Bs[buf][kc + 3][r] = rb[i].w;
        }
    };

    load_tiles(0);
    store_tiles(0);
    __syncthreads();

    for (int t = 0; t < NT; t++) {
        int cur = t & 1;
        if (t + 1 < NT) load_tiles(t + 1);
#pragma unroll
        for (int k = 0; k < BK; k++) {
            float a[TM], b[TN];
            const float4 a0 = *(const float4*)&As[cur][k][tx * 4];
            a[0] = a0.x; a[1] = a0.y; a[2] = a0.z; a[3] = a0.w;
            if (TM == 8) {
                const float4 a1 = *(const float4*)&As[cur][k][64 + tx * 4];
                a[4] = a1.x; a[5] = a1.y; a[6] = a1.z; a[7] = a1.w;
            }
            const float4 b0 = *(const float4*)&Bs[cur][k][ty * 4];
            b[0] = b0.x; b[1] = b0.y; b[2] = b0.z; b[3] = b0.w;
#pragma unroll
            for (int i = 0; i < TM; i++)
#pragma unroll
                for (int j = 0; j < TN; j++)
                    acc[i][j] = fmaf(a[i], b[j], acc[i][j]);
        }
        if (t + 1 < NT) store_tiles((t + 1) & 1);
        __syncthreads();
    }

#pragma unroll
    for (int i = 0; i < TM; i++) {
        int gm = m0 + (i >> 2) * 64 + (tx << 2) + (i & 3);
        if (gm >= M) continue;
        if (epil == 3) {
            float* Cp = C + ((size_t)blockIdx.z * M + gm) * N;
#pragma unroll
            for (int j = 0; j < TN; j++) {
                int gn = n0 + ty * TN + j;
                if (gn < N) Cp[gn] = acc[i][j];
            }
        } else {
            int bb = gm / HWp;
            int lhw = gm - bb * HWp;
            int ly = lhw / OWp, lx = lhw - ly * OWp;
            int hw = (py + sy * ly) * OWfull + (px + sx * lx);
            size_t base = ((size_t)bb * CO) * HWfull + hw;
#pragma unroll
            for (int j = 0; j < TN; j++) {
                int gn = n0 + ty * TN + j;
                if (gn >= N) continue;
                float v = acc[i][j] + bias[gn];
                if (epil == 1) v = (v >= 0.f) ? v : 0.01f * v;
                else if (epil == 2) v = fmaxf(v, 0.f);
                C[base + (size_t)gn * HWfull] = v;
            }
        }
    }
}

// ---------------- other kernels ----------------

__global__ void fill_costab(float* tab) {
    int k = blockIdx.x * blockDim.x + threadIdx.x;
    if (k < 800) tab[k] = (float)cos(2.0 * 3.141592653589793238462643 * (double)k / 800.0);
}

// forward-conv im2col, optional fused batchnorm on the input
__global__ void im2colF(const float* __restrict__ in, const float* __restrict__ mean,
                        const float* __restrict__ invstd, float* __restrict__ col,
                        int CI, int IH, int IW, int OH, int OW, int s, int p) {
    int row = blockIdx.x;
    int kk  = blockIdx.y * blockDim.x + threadIdx.x;
    int K = CI * 9;
    if (kk >= K) return;
    int OHW = OH * OW;
    int b = row / OHW, hw = row % OHW;
    int oy = hw / OW, ox = hw % OW;
    int ci = kk / 9, r = kk % 9, ky = r / 3, kx = r % 3;
    int iy = oy * s - p + ky, ix = ox * s - p + kx;
    float v = 0.f;
    if (iy >= 0 && iy < IH && ix >= 0 && ix < IW) {
        v = in[(((size_t)b * CI + ci) * IH + iy) * IW + ix];
        if (mean) v = (v - mean[ci]) * invstd[ci];
    }
    col[(size_t)row * K + kk] = v;
}

// parity-class im2col for stride-2 transposed convs (zero-free)
__global__ void im2colP(const float* __restrict__ in, float* __restrict__ col,
                        int CI, int IH, int IW, int OHp, int OWp,
                        int pd, int py, int px, int ky0, int nky, int kx0, int nkx) {
    int row = blockIdx.x;
    int kk  = blockIdx.y * blockDim.x + threadIdx.x;
    int Kt = CI * nky * nkx;
    if (kk >= Kt) return;
    int HWp = OHp * OWp;
    int b = row / HWp, r = row % HWp;
    int ly = r / OWp, lx = r % OWp;
    int oy = py + 2 * ly, ox = px + 2 * lx;
    int nt = nky * nkx;
    int ci = kk / nt, rr = kk % nt;
    int jy = rr / nkx, jx = rr % nkx;
    int ky = ky0 + 2 * jy, kx = kx0 + 2 * jx;
    int tyy = oy + ky - pd, txx = ox + kx - pd;   // always even by construction
    float v = 0.f;
    if (tyy >= 0 && txx >= 0) {
        int iy = tyy >> 1, ix = txx >> 1;
        if (iy < IH && ix < IW)
            v = in[(((size_t)b * CI + ci) * IH + iy) * IW + ix];
    }
    col[(size_t)row * Kt + kk] = v;
}

// convT weight per parity class: wt[co][ci*nt + jy*nkx + jx] = w[ci][co][2-ky][2-kx]
__global__ void wt_convT_p(const float* __restrict__ w, float* __restrict__ wt,
                           int CI, int CO, int ky0, int nky, int kx0, int nkx) {
    int idx = blockIdx.x * blockDim.x + threadIdx.x;
    int nt = nky * nkx;
    int total = CO * CI * nt;
    if (idx >= total) return;
    int co = idx / (CI * nt);
    int r = idx % (CI * nt);
    int ci = r / nt, rr = r % nt;
    int jy = rr / nkx, jx = rr % nkx;
    int ky = ky0 + 2 * jy, kx = kx0 + 2 * jx;
    wt[idx] = w[(((size_t)ci * CO + co) * 3 + (2 - ky)) * 3 + (2 - kx)];
}

// batchnorm stats: zero, partial (grid C x B), finalize
__global__ void bn_zero(float* s, float* ss, int C) {
    int i = blockIdx.x * blockDim.x + threadIdx.x;
    if (i < C) { s[i] = 0.f; ss[i] = 0.f; }
}
__global__ void bn_partial(const float* __restrict__ h, float* sum, float* sumsq,
                           int C, int HW) {
    int c = blockIdx.x, b = blockIdx.y;
    const float* p = h + ((size_t)b * C + c) * HW;
    float s = 0.f, ss = 0.f;
    for (int i = threadIdx.x; i < HW; i += blockDim.x) { float v = p[i]; s += v; ss += v * v; }
#pragma unroll
    for (int o = 16; o > 0; o >>= 1) {
        s  += __shfl_down_sync(0xffffffff, s, o);
        ss += __shfl_down_sync(0xffffffff, ss, o);
    }
    __shared__ float w1[4], w2[4];
    int wid = threadIdx.x >> 5, lid = threadIdx.x & 31;
    if (lid == 0) { w1[wid] = s; w2[wid] = ss; }
    __syncthreads();
    if (threadIdx.x == 0) {
        float S = 0.f, SS = 0.f;
        for (int i = 0; i < 4; i++) { S += w1[i]; SS += w2[i]; }
        atomicAdd(&sum[c], S);
        atomicAdd(&sumsq[c], SS);
    }
}
__global__ void bn_finalize(const float* sum, const float* sumsq, float* mean, float* invstd,
                            int C, float cnt) {
    int c = blockIdx.x * blockDim.x + threadIdx.x;
    if (c < C) {
        float m = sum[c] / cnt;
        float var = sumsq[c] / cnt - m * m;
        mean[c] = m;
        invstd[c] = rsqrtf(var + 1e-5f);
    }
}

__global__ void norm_inplace(float* h, const float* __restrict__ mean,
                             const float* __restrict__ invstd, int C, int HW, int total) {
    int idx = blockIdx.x * blockDim.x + threadIdx.x;
    if (idx >= total) return;
    int c = (idx / HW) % C;
    h[idx] = (h[idx] - mean[c]) * invstd[c];
}

// dst[N,K] = src[K,N]^T
__global__ void transpose_kn(const float* __restrict__ src, float* __restrict__ dst, int K, int N) {
    __shared__ float tile[32][33];
    int k0 = blockIdx.y * 32, n0 = blockIdx.x * 32;
    int tx = threadIdx.x, ty = threadIdx.y;
    for (int i = 0; i < 32; i += 8) {
        int k = k0 + ty + i, n = n0 + tx;
        if (k < K && n < N) tile[ty + i][tx] = src[(size_t)k * N + n];
    }
    __syncthreads();
    for (int i = 0; i < 32; i += 8) {
        int n = n0 + ty + i, k = k0 + tx;
        if (n < N && k < K) dst[(size_t)n * K + k] = tile[tx][ty + i];
    }
}

// split-K reduce for fc: sum partials, +bias, relu
__global__ void reduce_fc(const float* __restrict__ part, const float* __restrict__ bias,
                          float* __restrict__ out, int M, int N, int S) {
    int idx = blockIdx.x * blockDim.x + threadIdx.x;
    if (idx >= M * N) return;
    int m = idx / N, n = idx - m * N;
    float s = 0.f;
    for (int z = 0; z < S; z++) s += part[((size_t)z * M + m) * N + n];
    s += bias[n];
    out[idx] = fmaxf(s, 0.f);
}

// R[b, m*8+l] = sum_{m',l'} eig[b, m'*8+l'] * cos(2pi*(m*m'/100 + l*l'/8))
__global__ void compute_R(const float* __restrict__ eig, const float* __restrict__ tab,
                          float* __restrict__ R) {
    int b = blockIdx.x;
    __shared__ float s[800];
    __shared__ float t[800];
    for (int i = threadIdx.x; i < 800; i += 256) { s[i] = eig[b * 800 + i]; t[i] = tab[i]; }
    __syncthreads();
    for (int o = threadIdx.x; o < 800; o += 256) {
        int m = o >> 3, l = o & 7;
        float acc = 0.f;
        for (int q = 0; q < 800; q++) {
            int mp = q >> 3, lp = q & 7;
            int ph = (8 * m * mp + 100 * l * lp) % 800;
            acc += s[q] * t[ph];
        }
        R[b * 800 + o] = acc;
    }
}

// C[b,i,j] = R[b,(i-j) mod 800] / sqrt(800)
__global__ void write_C(const float* __restrict__ R, float* __restrict__ C) {
    int b = blockIdx.y;
    int i = blockIdx.x;
    __shared__ float r[800];
    const float inv = 0.035355339059327376f;
    for (int q = threadIdx.x; q < 800; q += 256) r[q] = R[b * 800 + q] * inv;
    __syncthreads();
    size_t base = ((size_t)b * 800 + i) * 800;
    for (int j = threadIdx.x; j < 800; j += 256)
        C[base + j] = r[(i - j + 800) % 800];
}

// ct5: direct conv (stride 1, effective pad 2, flipped kernel), N=1 output channel
__global__ void ct5_conv(const float* __restrict__ t4, const float* __restrict__ w,
                         const float* __restrict__ bias, float* __restrict__ out) {
    __shared__ float ws[576];
    for (int i = threadIdx.x; i < 576; i += blockDim.x) {
        int ci = i / 9, rr = i % 9, ky = rr / 3, kx = rr % 3;
        ws[i] = w[ci * 9 + (2 - ky) * 3 + (2 - kx)];
    }
    __syncthreads();
    int b = blockIdx.y;
    int o = blockIdx.x * blockDim.x + threadIdx.x;
    if (o >= 2401) return;
    int oy = o / 49, ox = o % 49;
    float acc = bias[0];
    for (int ci = 0; ci < 64; ci++) {
        const float* p = t4 + ((size_t)b * 64 + ci) * 47 * 47;
        const float* wc = ws + ci * 9;
#pragma unroll
        for (int ky = 0; ky < 3; ky++) {
            int iy = oy + ky - 2;
            if (iy < 0 || iy >= 47) continue;
#pragma unroll
            for (int kx = 0; kx < 3; kx++) {
                int ix = ox + kx - 2;
                if (ix < 0 || ix >= 47) continue;
                acc += p[iy * 47 + ix] * wc[ky * 3 + kx];
            }
        }
    }
    out[(size_t)b * 2401 + o] = acc;
}

// ---------------- host side ----------------

static float* symaddr(const void* s) {
    void* p = nullptr;
    cudaGetSymbolAddress(&p, s);
    return (float*)p;
}

static void launch_gemm(bool big, const float* A, const float* Bm, const float* bias, float* C,
                        int M, int N, int K, int lda, int ldb,
                        int CO, int HWp, int HWfull, int OWp, int OWfull,
                        int sy, int sx, int py, int px, int epil, int S = 1) {
    if (big) {
        dim3 g((N + 63) / 64, (M + 127) / 128, S);
        gemm_t<128, 64, 8, 4><<<g, 256>>>(A, Bm, bias, C, M, N, K, lda, ldb,
                                          CO, HWp, HWfull, OWp, OWfull, sy, sx, py, px, epil);
    } else {
        dim3 g((N + 63) / 64, (M + 63) / 64, S);
        gemm_t<64, 64, 4, 4><<<g, 256>>>(A, Bm, bias, C, M, N, K, lda, ldb,
                                         CO, HWp, HWfull, OWp, OWfull, sy, sx, py, px, epil);
    }
}

static void run_im2colF(const float* in, const float* mean, const float* invstd, float* col,
                        int B, int CI, int IH, int IW, int OH, int OW, int s, int p) {
    dim3 g(B * OH * OW, (CI * 9 + 255) / 256);
    im2colF<<<g, 256>>>(in, mean, invstd, col, CI, IH, IW, OH, OW, s, p);
}

static void run_bn(const float* h, int C, int HW) {
    float* sum = symaddr(g_bnsum);
    float* ss  = symaddr(g_bnss);
    bn_zero<<<(C + 255) / 256, 256>>>(sum, ss, C);
    bn_partial<<<dim3(C, 100), 128>>>(h, sum, ss, C, HW);
    bn_finalize<<<(C + 127) / 128, 128>>>(sum, ss, symaddr(g_mean), symaddr(g_invstd), C,
                                          100.f * (float)HW);
}

// stride-2 transposed conv via 4 parity-class dense GEMMs
static void convT_parity(const float* in, const float* w, const float* bias, float* outp,
                         int B, int CI, int CO, int IH, int IW, int OH, int OW, int pd) {
    float* col = symaddr(g_col);
    float* wT  = symaddr(g_wT);
    for (int py = 0; py < 2; py++) {
        for (int px = 0; px < 2; px++) {
            int ky0 = ((pd - py) % 2 + 2) % 2, nky = 2 - ky0;
            int kx0 = ((pd - px) % 2 + 2) % 2, nkx = 2 - kx0;
            int OHp = (OH - py + 1) / 2, OWp = (OW - px + 1) / 2;
            int Kt = CI * nky * nkx;
            int Mp = B * OHp * OWp;
            int tot = CO * Kt;
            wt_convT_p<<<(tot + 255) / 256, 256>>>(w, wT, CI, CO, ky0, nky, kx0, nkx);
            dim3 gi(Mp, (Kt + 255) / 256);
            im2colP<<<gi, 256>>>(in, col, CI, IH, IW, OHp, OWp, pd, py, px, ky0, nky, kx0, nkx);
            launch_gemm(Mp >= 8192, col, wT, bias, outp, Mp, CO, Kt, Kt, Kt,
                        CO, OHp * OWp, OH * OW, OWp, OW, 2, 2, py, px, 0);
        }
    }
}

extern "C" void kernel_launch(void* const* d_in, const int* in_sizes, int n_in,
                              void* d_out, int out_size) {
    const float* x       = (const float*)d_in[0];
    const float* conv1_w = (const float*)d_in[1];
    const float* conv1_b = (const float*)d_in[2];
    const float* conv2_w = (const float*)d_in[3];
    const float* conv2_b = (const float*)d_in[4];
    const float* conv3_w = (const float*)d_in[5];
    const float* conv3_b = (const float*)d_in[6];
    const float* conv4_w = (const float*)d_in[7];
    const float* conv4_b = (const float*)d_in[8];
    const float* fc_w    = (const float*)d_in[9];
    const float* fc_b    = (const float*)d_in[10];
    const float* dec_w   = (const float*)d_in[11];
    const float* dec_b   = (const float*)d_in[12];
    const float* ct1_w   = (const float*)d_in[13];
    const float* ct1_b   = (const float*)d_in[14];
    const float* ct2_w   = (const float*)d_in[15];
    const float* ct2_b   = (const float*)d_in[16];
    const float* ct3_w   = (const float*)d_in[17];
    const float* ct3_b   = (const float*)d_in[18];
    const float* ct4_w   = (const float*)d_in[19];
    const float* ct4_b   = (const float*)d_in[20];
    const float* ct5_w   = (const float*)d_in[21];
    const float* ct5_b   = (const float*)d_in[22];

    float* out = (float*)d_out;
    float* out_d   = out;                        // 100*49*49
    float* out_C   = out + 240100;               // 100*800*800
    float* out_eig = out + 240100 + 64000000;    // 100*800

    float* col  = symaddr(g_col);
    float* wT   = symaddr(g_wT);
    float* h1   = symaddr(g_h1);
    float* h2   = symaddr(g_h2);
    float* h3   = symaddr(g_h3);
    float* h4   = symaddr(g_h4);
    float* R    = symaddr(g_R);
    float* tab  = symaddr(g_tab);
    float* mean = symaddr(g_mean);
    float* ivs  = symaddr(g_invstd);
    float* d0   = symaddr(g_d0);
    float* t1   = symaddr(g_t1);
    float* t2   = symaddr(g_t2);
    float* t3   = symaddr(g_t3);
    float* t4   = symaddr(g_t4);

    const int B = 100;

    fill_costab<<<4, 256>>>(tab);

    // ---- encoder ----
    // conv1: 1 -> 128, 64 -> 32 (K=9, scalar-load path)
    run_im2colF(x, nullptr, nullptr, col, B, 1, 64, 64, 32, 32, 2, 1);
    launch_gemm(true, col, conv1_w, conv1_b, h1, B * 1024, 128, 9, 9, 9,
                128, 1024, 1024, 32, 32, 1, 1, 0, 0, 1);
    run_bn(h1, 128, 1024);

    // conv2: 128 -> 256, 32 -> 16 (BN of h1 fused into im2col)
    run_im2colF(h1, mean, ivs, col, B, 128, 32, 32, 16, 16, 2, 1);
    launch_gemm(true, col, conv2_w, conv2_b, h2, B * 256, 256, 1152, 1152, 1152,
                256, 256, 256, 16, 16, 1, 1, 0, 0, 1);
    run_bn(h2, 256, 256);

    // conv3: 256 -> 1024, 16 -> 8
    run_im2colF(h2, mean, ivs, col, B, 256, 16, 16, 8, 8, 2, 1);
    launch_gemm(true, col, conv3_w, conv3_b, h3, B * 64, 1024, 2304, 2304, 2304,
                1024, 64, 64, 8, 8, 1, 1, 0, 0, 1);
    run_bn(h3, 1024, 64);

    // conv4: 1024 -> 1024, 8 -> 4
    run_im2colF(h3, mean, ivs, col, B, 1024, 8, 8, 4, 4, 2, 1);
    launch_gemm(false, col, conv4_w, conv4_b, h4, B * 16, 1024, 9216, 9216, 9216,
                1024, 16, 16, 4, 4, 1, 1, 0, 0, 1);
    run_bn(h4, 1024, 16);
    norm_inplace<<<(1638400 + 255) / 256, 256>>>(h4, mean, ivs, 1024, 16, 1638400);

    // fc: (100,16384) @ (16384,800), split-K=8 into g_col partials, then reduce+relu
    {
        dim3 g((800 + 31) / 32, (16384 + 31) / 32);
        transpose_kn<<<g, dim3(32, 8)>>>(fc_w, wT, 16384, 800);
    }
    launch_gemm(false, h4, wT, fc_b, col, 100, 800, 2048, 16384, 16384,
                800, 1, 1, 1, 1, 1, 1, 0, 0, 3, /*S=*/8);
    reduce_fc<<<(80000 + 255) / 256, 256>>>(col, fc_b, out_eig, 100, 800, 8);

    // ---- spectral part ----
    compute_R<<<B, 256>>>(out_eig, tab, R);
    write_C<<<dim3(800, B), 256>>>(R, out_C);

    // dec: (100,800) @ (800,9216) -> d0
    {
        dim3 g((9216 + 31) / 32, (800 + 31) / 32);
        transpose_kn<<<g, dim3(32, 8)>>>(dec_w, wT, 800, 9216);
    }
    launch_gemm(false, R, wT, dec_b, d0, 100, 9216, 800, 800, 800,
                9216, 1, 1, 1, 1, 1, 1, 0, 0, 0);

    // ---- decoder: parity-decomposed transposed convs ----
    convT_parity(d0, ct1_w, ct1_b, t1, B, 1024, 512, 3, 3, 5, 5, /*pd=*/1);
    convT_parity(t1, ct2_w, ct2_b, t2, B, 512, 256, 5, 5, 11, 11, /*pd=*/2);
    convT_parity(t2, ct3_w, ct3_b, t3, B, 256, 128, 11, 11, 23, 23, /*pd=*/2);
    convT_parity(t3, ct4_w, ct4_b, t4, B, 128, 64, 23, 23, 47, 47, /*pd=*/2);

    // ct5: direct conv 64 -> 1, 47 -> 49
    ct5_conv<<<dim3((2401 + 255) / 256, B), 256>>>(t4, ct5_w, ct5_b, out_d);
}

// round 3
// speedup vs baseline: 3.1074x; 1.1163x over previous
#include <cuda_runtime.h>
#include <math.h>

// ---------------- scratch (__device__ globals; no allocs allowed) ----------------
__device__ float g_col[29600000];   // max im2col: conv2 = 25600 x 1152
__device__ float g_wT[13200000];    // max: fc_w^T = 800 x 16384
__device__ float g_h1[13107200];    // 100x128x32x32
__device__ float g_h2[6553600];     // 100x256x16x16
__device__ float g_h3[6553600];     // 100x1024x8x8
__device__ float g_h4[1638400];     // 100x1024x4x4
__device__ float g_R[80000];        // 100x800
__device__ float g_tab[800];
__device__ float g_mean[1024];
__device__ float g_invstd[1024];
__device__ float g_d0[921600];      // 100x1024x3x3
__device__ float g_t1[1280000];     // 100x512x5x5
__device__ float g_t2[3097600];     // 100x256x11x11
__device__ float g_t3[6771200];     // 100x128x23x23
__device__ float g_t4[14137600];    // 100x64x47x47

// ---------------- packed f32x2 helpers ----------------
__device__ __forceinline__ unsigned long long pack2(float v) {
    unsigned long long r;
    asm("mov.b64 %0, {%1, %1};" : "=l"(r) : "f"(v));
    return r;
}
__device__ __forceinline__ void fma2(unsigned long long& acc, unsigned long long a,
                                     unsigned long long b) {
    asm("fma.rn.f32x2 %0, %1, %2, %0;" : "+l"(acc) : "l"(a), "l"(b));
}
__device__ __forceinline__ float2 unpack2(unsigned long long v) {
    float lo, hi;
    asm("mov.b64 {%0, %1}, %2;" : "=f"(lo), "=f"(hi) : "l"(v));
    return make_float2(lo, hi);
}

// ---------------- GEMM: C = A[M,K] @ B[N,K]^T, double-buffered, f32x2 core -----
// epil: 0 none, 1 leaky, 2 relu, 3 raw split-K partial (C[(z*M+gm)*N+gn])
// scatter: b = gm/HWp, hw = (py + sy*(lhw/OWp))*OWfull + (px + sx*(lhw%OWp))
template<int BM, int BN, int TM, int TN>
__global__ void __launch_bounds__(256, 2)
gemm_t(const float* __restrict__ A, const float* __restrict__ Bm,
       const float* __restrict__ bias, float* __restrict__ C,
       int M, int N, int K, int lda, int ldb,
       int CO, int HWp, int HWfull, int OWp, int OWfull,
       int sy, int sx, int py, int px, int epil)
{
    constexpr int BK = 16;
    constexpr int NVA = (BM * BK) / (4 * 256);
    constexpr int NVB = (BN * BK) / (4 * 256);
    constexpr int TP = TM / 2;       // packed row-pairs
    __shared__ __align__(16) float As[2][BK][BM + 4];
    __shared__ __align__(16) float Bs[2][BK][BN + 4];
    const int tid = threadIdx.x;
    const int tx = tid & 15;    // M direction (fine)
    const int ty = tid >> 4;    // N direction
    const int m0 = blockIdx.y * BM;
    const int n0 = blockIdx.x * BN;
    const int koff = blockIdx.z * K;
    const bool vecOK = ((K & 15) == 0) && ((lda & 3) == 0) && ((ldb & 3) == 0);
    const int NT = (K + BK - 1) / BK;

    unsigned long long acc2[TP][TN];
#pragma unroll
    for (int p = 0; p < TP; p++)
#pragma unroll
        for (int j = 0; j < TN; j++) acc2[p][j] = 0ull;

    float4 ra[NVA], rb[NVB];

    auto load_tiles = [&](int t) {
        const int k0 = koff + t * BK;
        if (vecOK) {
#pragma unroll
            for (int i = 0; i < NVA; i++) {
                int vid = tid + i * 256;
                int r = vid >> 2, kc = (vid & 3) << 2;
                int gm = m0 + r;
                ra[i] = (gm < M) ? *(const float4*)(A + (size_t)gm * lda + k0 + kc)
                                 : make_float4(0.f, 0.f, 0.f, 0.f);
            }
#pragma unroll
            for (int i = 0; i < NVB; i++) {
                int vid = tid + i * 256;
                int r = vid >> 2, kc = (vid & 3) << 2;
                int gn = n0 + r;
                rb[i] = (gn < N) ? *(const float4*)(Bm + (size_t)gn * ldb + k0 + kc)
                                 : make_float4(0.f, 0.f, 0.f, 0.f);
            }
        } else {
            const int kend = koff + K;
#pragma unroll
            for (int i = 0; i < NVA; i++) {
                int vid = tid + i * 256;
                int r = vid >> 2, kc = (vid & 3) << 2;
                int gm = m0 + r;
                float v[4];
#pragma unroll
                for (int j = 0; j < 4; j++) {
                    int gk = k0 + kc + j;
                    v[j] = (gm < M && gk < kend) ? A[(size_t)gm * lda + gk] : 0.f;
                }
                ra[i] = make_float4(v[0], v[1], v[2], v[3]);
            }
#pragma unroll
            for (int i = 0; i < NVB; i++) {
                int vid = tid + i * 256;
                int r = vid >> 2, kc = (vid & 3) << 2;
                int gn = n0 + r;
                float v[4];
#pragma unroll
                for (int j = 0; j < 4; j++) {
                    int gk = k0 + kc + j;
                    v[j] = (gn < N && gk < kend) ? Bm[(size_t)gn * ldb + gk] : 0.f;
                }
                rb[i] = make_float4(v[0], v[1], v[2], v[3]);
            }
        }
    };
    auto store_tiles = [&](int buf) {
#pragma unroll
        for (int i = 0; i < NVA; i++) {
            int vid = tid + i * 256;
            int r = vid >> 2, kc = (vid & 3) << 2;
            As[buf][kc + 0][r] = ra[i].x;
            As[buf][kc + 1][r] = ra[i].y;
            As[buf][kc + 2][r] = ra[i].z;
            As[buf][kc + 3][r] = ra[i].w;
        }
#pragma unroll
        for (int i = 0; i < NVB; i++) {
            int vid = tid + i * 256;
            int r = vid >> 2, kc = (vid & 3) << 2;
            Bs[buf][kc + 0][r] = rb[i].x;
            Bs[buf][kc + 1][r] = rb[i].y;
            Bs[buf][kc + 2][r] = rb[i].z;
            Bs[buf][kc + 3][r] = rb[i].w;
        }
    };

    load_tiles(0);
    store_tiles(0);
    __syncthreads();

    for (int t = 0; t < NT; t++) {
        int cur = t & 1;
        if (t + 1 < NT) load_tiles(t + 1);
#pragma unroll
        for (int k = 0; k < BK; k++) {
            unsigned long long ap[TP];
            {
                const ulonglong2 av0 = *(const ulonglong2*)&As[cur][k][tx * 4];
                ap[0] = av0.x; ap[1] = av0.y;
                if (TP == 4) {
                    const ulonglong2 av1 = *(const ulonglong2*)&As[cur][k][64 + tx * 4];
                    ap[2] = av1.x; ap[3] = av1.y;
                }
            }
            const float4 b4 = *(const float4*)&Bs[cur][k][ty * 4];
            unsigned long long bb[TN];
            bb[0] = pack2(b4.x); bb[1] = pack2(b4.y);
            bb[2] = pack2(b4.z); bb[3] = pack2(b4.w);
#pragma unroll
            for (int p = 0; p < TP; p++)
#pragma unroll
                for (int j = 0; j < TN; j++)
                    fma2(acc2[p][j], ap[p], bb[j]);
        }
        if (t + 1 < NT) store_tiles((t + 1) & 1);
        __syncthreads();
    }

#pragma unroll
    for (int p = 0; p < TP; p++) {
        float2 vv[TN];
#pragma unroll
        for (int j = 0; j < TN; j++) vv[j] = unpack2(acc2[p][j]);
#pragma unroll
        for (int e = 0; e < 2; e++) {
            int gm = m0 + (p >> 1) * 64 + (tx << 2) + ((p & 1) << 1) + e;
            if (gm >= M) continue;
            if (epil == 3) {
                float* Cp = C + ((size_t)blockIdx.z * M + gm) * N;
#pragma unroll
                for (int j = 0; j < TN; j++) {
                    int gn = n0 + ty * TN + j;
                    if (gn < N) Cp[gn] = e ? vv[j].y : vv[j].x;
                }
            } else {
                int bb2 = gm / HWp;
                int lhw = gm - bb2 * HWp;
                int ly = lhw / OWp, lx = lhw - ly * OWp;
                int hw = (py + sy * ly) * OWfull + (px + sx * lx);
                size_t base = ((size_t)bb2 * CO) * HWfull + hw;
#pragma unroll
                for (int j = 0; j < TN; j++) {
                    int gn = n0 + ty * TN + j;
                    if (gn >= N) continue;
                    float v = (e ? vv[j].y : vv[j].x) + bias[gn];
                    if (epil == 1) v = (v >= 0.f) ? v : 0.01f * v;
                    else if (epil == 2) v = fmaxf(v, 0.f);
                    C[base + (size_t)gn * HWfull] = v;
                }
            }
        }
    }
}

// ---------------- other kernels ----------------

// conv1 fused direct: 1->128, 64->64 -> 32x32, stride 2 pad 1, + leaky
__global__ void conv1_direct(const float* __restrict__ x, const float* __restrict__ w,
                             const float* __restrict__ bias, float* __restrict__ h1) {
    __shared__ float ws[1152];
    __shared__ float bs[128];
    for (int i = threadIdx.x; i < 1152; i += 256) ws[i] = w[i];
    for (int i = threadIdx.x; i < 128; i += 256) bs[i] = bias[i];
    __syncthreads();
    int b = blockIdx.y;
    int hw = blockIdx.x * 256 + threadIdx.x;
    int oy = hw >> 5, ox = hw & 31;
    float xv[9];
#pragma unroll
    for (int ky = 0; ky < 3; ky++)
#pragma unroll
        for (int kx = 0; kx < 3; kx++) {
            int iy = 2 * oy - 1 + ky, ix = 2 * ox - 1 + kx;
            xv[ky * 3 + kx] = (iy >= 0 && iy < 64 && ix >= 0 && ix < 64)
                                  ? x[(size_t)b * 4096 + iy * 64 + ix] : 0.f;
        }
    for (int co = 0; co < 128; co++) {
        float acc = bs[co];
        const float* wc = ws + co * 9;
#pragma unroll
        for (int t = 0; t < 9; t++) acc = fmaf(xv[t], wc[t], acc);
        acc = (acc >= 0.f) ? acc : 0.01f * acc;
        h1[((size_t)b * 128 + co) * 1024 + hw] = acc;
    }
}

// single-kernel batchnorm stats: one block per channel
__global__ void bn_stats(const float* __restrict__ h, float* mean, float* invstd,
                         int C, int Bn, int HW) {
    int c = blockIdx.x;
    float s = 0.f, ss = 0.f;
    for (int b = 0; b < Bn; b++) {
        const float* p = h + ((size_t)b * C + c) * HW;
        for (int i = threadIdx.x; i < HW; i += 512) {
            float v = p[i];
            s += v; ss += v * v;
        }
    }
    __shared__ float rs[512], rss[512];
    rs[threadIdx.x] = s; rss[threadIdx.x] = ss;
    __syncthreads();
    for (int st = 256; st > 0; st >>= 1) {
        if (threadIdx.x < st) { rs[threadIdx.x] += rs[threadIdx.x + st]; rss[threadIdx.x] += rss[threadIdx.x + st]; }
        __syncthreads();
    }
    if (threadIdx.x == 0) {
        float cnt = (float)Bn * (float)HW;
        float m = rs[0] / cnt;
        float var = rss[0] / cnt - m * m;
        mean[c] = m;
        invstd[c] = rsqrtf(var + 1e-5f);
    }
}

__global__ void fill_costab(float* tab) {
    int k = blockIdx.x * blockDim.x + threadIdx.x;
    if (k < 800) tab[k] = (float)cos(2.0 * 3.141592653589793238462643 * (double)k / 800.0);
}

// forward-conv im2col with fused batchnorm on the input
__global__ void im2colF(const float* __restrict__ in, const float* __restrict__ mean,
                        const float* __restrict__ invstd, float* __restrict__ col,
                        int CI, int IH, int IW, int OH, int OW, int s, int p) {
    int row = blockIdx.x;
    int kk  = blockIdx.y * blockDim.x + threadIdx.x;
    int K = CI * 9;
    if (kk >= K) return;
    int OHW = OH * OW;
    int b = row / OHW, hw = row % OHW;
    int oy = hw / OW, ox = hw % OW;
    int ci = kk / 9, r = kk % 9, ky = r / 3, kx = r % 3;
    int iy = oy * s - p + ky, ix = ox * s - p + kx;
    float v = 0.f;
    if (iy >= 0 && iy < IH && ix >= 0 && ix < IW) {
        v = in[(((size_t)b * CI + ci) * IH + iy) * IW + ix];
        v = (v - mean[ci]) * invstd[ci];
    }
    col[(size_t)row * K + kk] = v;
}

// parity-class im2col for stride-2 transposed convs (zero-free)
__global__ void im2colP(const float* __restrict__ in, float* __restrict__ col,
                        int CI, int IH, int IW, int OHp, int OWp,
                        int pd, int py, int px, int ky0, int nky, int kx0, int nkx) {
    int row = blockIdx.x;
    int kk  = blockIdx.y * blockDim.x + threadIdx.x;
    int Kt = CI * nky * nkx;
    if (kk >= Kt) return;
    int HWp = OHp * OWp;
    int b = row / HWp, r = row % HWp;
    int ly = r / OWp, lx = r % OWp;
    int oy = py + 2 * ly, ox = px + 2 * lx;
    int nt = nky * nkx;
    int ci = kk / nt, rr = kk % nt;
    int jy = rr / nkx, jx = rr % nkx;
    int ky = ky0 + 2 * jy, kx = kx0 + 2 * jx;
    int tyy = oy + ky - pd, txx = ox + kx - pd;   // always even by construction
    float v = 0.f;
    if (tyy >= 0 && txx >= 0) {
        int iy = tyy >> 1, ix = txx >> 1;
        if (iy < IH && ix < IW)
            v = in[(((size_t)b * CI + ci) * IH + iy) * IW + ix];
    }
    col[(size_t)row * Kt + kk] = v;
}

// convT weight per parity class: wt[co][ci*nt + jy*nkx + jx] = w[ci][co][2-ky][2-kx]
__global__ void wt_convT_p(const float* __restrict__ w, float* __restrict__ wt,
                           int CI, int CO, int ky0, int nky, int kx0, int nkx) {
    int idx = blockIdx.x * blockDim.x + threadIdx.x;
    int nt = nky * nkx;
    int total = CO * CI * nt;
    if (idx >= total) return;
    int co = idx / (CI * nt);
    int r = idx % (CI * nt);
    int ci = r / nt, rr = r % nt;
    int jy = rr / nkx, jx = rr % nkx;
    int ky = ky0 + 2 * jy, kx = kx0 + 2 * jx;
    wt[idx] = w[(((size_t)ci * CO + co) * 3 + (2 - ky)) * 3 + (2 - kx)];
}

__global__ void norm_inplace(float* h, const float* __restrict__ mean,
                             const float* __restrict__ invstd, int C, int HW, int total) {
    int idx = blockIdx.x * blockDim.x + threadIdx.x;
    if (idx >= total) return;
    int c = (idx / HW) % C;
    h[idx] = (h[idx] - mean[c]) * invstd[c];
}

// dst[N,K] = src[K,N]^T
__global__ void transpose_kn(const float* __restrict__ src, float* __restrict__ dst, int K, int N) {
    __shared__ float tile[32][33];
    int k0 = blockIdx.y * 32, n0 = blockIdx.x * 32;
    int tx = threadIdx.x, ty = threadIdx.y;
    for (int i = 0; i < 32; i += 8) {
        int k = k0 + ty + i, n = n0 + tx;
        if (k < K && n < N) tile[ty + i][tx] = src[(size_t)k * N + n];
    }
    __syncthreads();
    for (int i = 0; i < 32; i += 8) {
        int n = n0 + ty + i, k = k0 + tx;
        if (n < N && k < K) dst[(size_t)n * K + k] = tile[tx][ty + i];
    }
}

// split-K reduce for fc: sum partials, +bias, relu
__global__ void reduce_fc(const float* __restrict__ part, const float* __restrict__ bias,
                          float* __restrict__ out, int M, int N, int S) {
    int idx = blockIdx.x * blockDim.x + threadIdx.x;
    if (idx >= M * N) return;
    int m = idx / N, n = idx - m * N;
    float s = 0.f;
    for (int z = 0; z < S; z++) s += part[((size_t)z * M + m) * N + n];
    s += bias[n];
    out[idx] = fmaxf(s, 0.f);
}

// R[b, m*8+l] = sum_{m',l'} eig[b, m'*8+l'] * cos(2pi*(m*m'/100 + l*l'/8))
__global__ void compute_R(const float* __restrict__ eig, const float* __restrict__ tab,
                          float* __restrict__ R) {
    int b = blockIdx.x;
    __shared__ float s[800];
    __shared__ float t[800];
    for (int i = threadIdx.x; i < 800; i += 256) { s[i] = eig[b * 800 + i]; t[i] = tab[i]; }
    __syncthreads();
    for (int o = threadIdx.x; o < 800; o += 256) {
        int m = o >> 3, l = o & 7;
        float acc = 0.f;
        for (int q = 0; q < 800; q++) {
            int mp = q >> 3, lp = q & 7;
            int ph = (8 * m * mp + 100 * l * lp) % 800;
            acc += s[q] * t[ph];
        }
        R[b * 800 + o] = acc;
    }
}

// C[b,i,j] = R[b,(i-j) mod 800] / sqrt(800)
__global__ void write_C(const float* __restrict__ R, float* __restrict__ C) {
    int b = blockIdx.y;
    int i = blockIdx.x;
    __shared__ float r[800];
    const float inv = 0.035355339059327376f;
    for (int q = threadIdx.x; q < 800; q += 256) r[q] = R[b * 800 + q] * inv;
    __syncthreads();
    size_t base = ((size_t)b * 800 + i) * 800;
    for (int j = threadIdx.x; j < 256; j += 256) ;
    for (int j = threadIdx.x; j < 800; j += 256)
        C[base + j] = r[(i - j + 800) % 800];
}

// ct5: direct conv (stride 1, effective pad 2, flipped kernel), N=1 output channel
__global__ void ct5_conv(const float* __restrict__ t4, const float* __restrict__ w,
                         const float* __restrict__ bias, float* __restrict__ out) {
    __shared__ float ws[576];
    for (int i = threadIdx.x; i < 576; i += blockDim.x) {
        int ci = i / 9, rr = i % 9, ky = rr / 3, kx = rr % 3;
        ws[i] = w[ci * 9 + (2 - ky) * 3 + (2 - kx)];
    }
    __syncthreads();
    int b = blockIdx.y;
    int o = blockIdx.x * blockDim.x + threadIdx.x;
    if (o >= 2401) return;
    int oy = o / 49, ox = o % 49;
    float acc = bias[0];
    for (int ci = 0; ci < 64; ci++) {
        const float* p = t4 + ((size_t)b * 64 + ci) * 47 * 47;
        const float* wc = ws + ci * 9;
#pragma unroll
        for (int ky = 0; ky < 3; ky++) {
            int iy = oy + ky - 2;
            if (iy < 0 || iy >= 47) continue;
#pragma unroll
            for (int kx = 0; kx < 3; kx++) {
                int ix = ox + kx - 2;
                if (ix < 0 || ix >= 47) continue;
                acc += p[iy * 47 + ix] * wc[ky * 3 + kx];
            }
        }
    }
    out[(size_t)b * 2401 + o] = acc;
}

// ---------------- host side ----------------

static float* symaddr(const void* s) {
    void* p = nullptr;
    cudaGetSymbolAddress(&p, s);
    return (float*)p;
}

static void launch_gemm(bool big, const float* A, const float* Bm, const float* bias, float* C,
                        int M, int N, int K, int lda, int ldb,
                        int CO, int HWp, int HWfull, int OWp, int OWfull,
                        int sy, int sx, int py, int px, int epil, int S = 1) {
    if (big) {
        dim3 g((N + 63) / 64, (M + 127) / 128, S);
        gemm_t<128, 64, 8, 4><<<g, 256>>>(A, Bm, bias, C, M, N, K, lda, ldb,
                                          CO, HWp, HWfull, OWp, OWfull, sy, sx, py, px, epil);
    } else {
        dim3 g((N + 63) / 64, (M + 63) / 64, S);
        gemm_t<64, 64, 4, 4><<<g, 256>>>(A, Bm, bias, C, M, N, K, lda, ldb,
                                         CO, HWp, HWfull, OWp, OWfull, sy, sx, py, px, epil);
    }
}

static void run_im2colF(const float* in, const float* mean, const float* invstd, float* col,
                        int B, int CI, int IH, int IW, int OH, int OW, int s, int p) {
    dim3 g(B * OH * OW, (CI * 9 + 255) / 256);
    im2colF<<<g, 256>>>(in, mean, invstd, col, CI, IH, IW, OH, OW, s, p);
}

// stride-2 transposed conv via 4 parity-class dense GEMMs
static void convT_parity(const float* in, const float* w, const float* bias, float* outp,
                         int B, int CI, int CO, int IH, int IW, int OH, int OW, int pd) {
    float* col = symaddr(g_col);
    float* wT  = symaddr(g_wT);
    for (int py = 0; py < 2; py++) {
        for (int px = 0; px < 2; px++) {
            int ky0 = ((pd - py) % 2 + 2) % 2, nky = 2 - ky0;
            int kx0 = ((pd - px) % 2 + 2) % 2, nkx = 2 - kx0;
            int OHp = (OH - py + 1) / 2, OWp = (OW - px + 1) / 2;
            int Kt = CI * nky * nkx;
            int Mp = B * OHp * OWp;
            int tot = CO * Kt;
            wt_convT_p<<<(tot + 255) / 256, 256>>>(w, wT, CI, CO, ky0, nky, kx0, nkx);
            dim3 gi(Mp, (Kt + 255) / 256);
            im2colP<<<gi, 256>>>(in, col, CI, IH, IW, OHp, OWp, pd, py, px, ky0, nky, kx0, nkx);
            launch_gemm(Mp >= 8192, col, wT, bias, outp, Mp, CO, Kt, Kt, Kt,
                        CO, OHp * OWp, OH * OW, OWp, OW, 2, 2, py, px, 0);
        }
    }
}

extern "C" void kernel_launch(void* const* d_in, const int* in_sizes, int n_in,
                              void* d_out, int out_size) {
    const float* x       = (const float*)d_in[0];
    const float* conv1_w = (const float*)d_in[1];
    const float* conv1_b = (const float*)d_in[2];
    const float* conv2_w = (const float*)d_in[3];
    const float* conv2_b = (const float*)d_in[4];
    const float* conv3_w = (const float*)d_in[5];
    const float* conv3_b = (const float*)d_in[6];
    const float* conv4_w = (const float*)d_in[7];
    const float* conv4_b = (const float*)d_in[8];
    const float* fc_w    = (const float*)d_in[9];
    const float* fc_b    = (const float*)d_in[10];
    const float* dec_w   = (const float*)d_in[11];
    const float* dec_b   = (const float*)d_in[12];
    const float* ct1_w   = (const float*)d_in[13];
    const float* ct1_b   = (const float*)d_in[14];
    const float* ct2_w   = (const float*)d_in[15];
    const float* ct2_b   = (const float*)d_in[16];
    const float* ct3_w   = (const float*)d_in[17];
    const float* ct3_b   = (const float*)d_in[18];
    const float* ct4_w   = (const float*)d_in[19];
    const float* ct4_b   = (const float*)d_in[20];
    const float* ct5_w   = (const float*)d_in[21];
    const float* ct5_b   = (const float*)d_in[22];

    float* out = (float*)d_out;
    float* out_d   = out;                        // 100*49*49
    float* out_C   = out + 240100;               // 100*800*800
    float* out_eig = out + 240100 + 64000000;    // 100*800

    float* col  = symaddr(g_col);
    float* wT   = symaddr(g_wT);
    float* h1   = symaddr(g_h1);
    float* h2   = symaddr(g_h2);
    float* h3   = symaddr(g_h3);
    float* h4   = symaddr(g_h4);
    float* R    = symaddr(g_R);
    float* tab  = symaddr(g_tab);
    float* mean = symaddr(g_mean);
    float* ivs  = symaddr(g_invstd);
    float* d0   = symaddr(g_d0);
    float* t1   = symaddr(g_t1);
    float* t2   = symaddr(g_t2);
    float* t3   = symaddr(g_t3);
    float* t4   = symaddr(g_t4);

    const int B = 100;

    // ---- encoder ----
    // conv1: direct fused kernel (launch #1)
    conv1_direct<<<dim3(4, B), 256>>>(x, conv1_w, conv1_b, h1);
    bn_stats<<<128, 512>>>(h1, mean, ivs, 128, B, 1024);          // #2

    // conv2: 128 -> 256, 32 -> 16 (BN of h1 fused into im2col)
    run_im2colF(h1, mean, ivs, col, B, 128, 32, 32, 16, 16, 2, 1); // #3
    launch_gemm(true, col, conv2_w, conv2_b, h2, B * 256, 256, 1152, 1152, 1152,
                256, 256, 256, 16, 16, 1, 1, 0, 0, 1);             // #4 (profiled)
    bn_stats<<<256, 512>>>(h2, mean, ivs, 256, B, 256);

    // conv3: 256 -> 1024, 16 -> 8
    run_im2colF(h2, mean, ivs, col, B, 256, 16, 16, 8, 8, 2, 1);
    launch_gemm(true, col, conv3_w, conv3_b, h3, B * 64, 1024, 2304, 2304, 2304,
                1024, 64, 64, 8, 8, 1, 1, 0, 0, 1);
    bn_stats<<<1024, 512>>>(h3, mean, ivs, 1024, B, 64);

    // conv4: 1024 -> 1024, 8 -> 4
    run_im2colF(h3, mean, ivs, col, B, 1024, 8, 8, 4, 4, 2, 1);
    launch_gemm(false, col, conv4_w, conv4_b, h4, B * 16, 1024, 9216, 9216, 9216,
                1024, 16, 16, 4, 4, 1, 1, 0, 0, 1);
    bn_stats<<<1024, 512>>>(h4, mean, ivs, 1024, B, 16);
    norm_inplace<<<(1638400 + 255) / 256, 256>>>(h4, mean, ivs, 1024, 16, 1638400);

    // fc: (100,16384) @ (16384,800), split-K=8 into g_col partials, then reduce+relu
    {
        dim3 g((800 + 31) / 32, (16384 + 31) / 32);
        transpose_kn<<<g, dim3(32, 8)>>>(fc_w, wT, 16384, 800);
    }
    launch_gemm(false, h4, wT, fc_b, col, 100, 800, 2048, 16384, 16384,
                800, 1, 1, 1, 1, 1, 1, 0, 0, 3, /*S=*/8);
    reduce_fc<<<(80000 + 255) / 256, 256>>>(col, fc_b, out_eig, 100, 800, 8);

    // ---- spectral part ----
    fill_costab<<<4, 256>>>(tab);
    compute_R<<<B, 256>>>(out_eig, tab, R);
    write_C<<<dim3(800, B), 256>>>(R, out_C);

    // dec: (100,800) @ (800,9216) -> d0
    {
        dim3 g((9216 + 31) / 32, (800 + 31) / 32);
        transpose_kn<<<g, dim3(32, 8)>>>(dec_w, wT, 800, 9216);
    }
    launch_gemm(false, R, wT, dec_b, d0, 100, 9216, 800, 800, 800,
                9216, 1, 1, 1, 1, 1, 1, 0, 0, 0);

    // ---- decoder: parity-decomposed transposed convs ----
    convT_parity(d0, ct1_w, ct1_b, t1, B, 1024, 512, 3, 3, 5, 5, /*pd=*/1);
    convT_parity(t1, ct2_w, ct2_b, t2, B, 512, 256, 5, 5, 11, 11, /*pd=*/2);
    convT_parity(t2, ct3_w, ct3_b, t3, B, 256, 128, 11, 11, 23, 23, /*pd=*/2);
    convT_parity(t3, ct4_w, ct4_b, t4, B, 128, 64, 23, 23, 47, 47, /*pd=*/2);

    // ct5: direct conv 64 -> 1, 47 -> 49
    ct5_conv<<<dim3((2401 + 255) / 256, B), 256>>>(t4, ct5_w, ct5_b, out_d);
}

// round 4
// speedup vs baseline: 3.5619x; 1.1462x over previous
#include <cuda_runtime.h>
#include <math.h>

// ---------------- scratch (__device__ globals) ----------------
__device__ float g_col[66000000];   // batched parity im2col (ct4 total 64.5M) / conv2 29.5M
__device__ float g_wT[13200000];    // per-layer parity weight slices (<= 9*CO*CI)
__device__ float g_h1[13107200];    // 100x128x32x32
__device__ float g_h2[6553600];     // 100x256x16x16
__device__ float g_h3[6553600];     // 100x1024x8x8
__device__ float g_h4[1638400];     // 100x1024x4x4
__device__ float g_part[6553600];   // split-K partials: conv4 4x1600x1024, fc 8x100x800
__device__ float g_R[80000];
__device__ float g_tab[800];
__device__ float g_mean[1024];
__device__ float g_invstd[1024];
__device__ float g_d0[921600];      // 100x1024x3x3
__device__ float g_t1[1280000];     // 100x512x5x5
__device__ float g_t2[3097600];     // 100x256x11x11
__device__ float g_t3[6771200];     // 100x128x23x23
__device__ float g_t4[14137600];    // 100x64x47x47

// ---------------- packed f32x2 helpers ----------------
__device__ __forceinline__ unsigned long long pack2(float v) {
    unsigned long long r;
    asm("mov.b64 %0, {%1, %1};" : "=l"(r) : "f"(v));
    return r;
}
__device__ __forceinline__ void fma2(unsigned long long& acc, unsigned long long a,
                                     unsigned long long b) {
    asm("fma.rn.f32x2 %0, %1, %2, %0;" : "+l"(acc) : "l"(a), "l"(b));
}
__device__ __forceinline__ float2 unpack2(unsigned long long v) {
    float lo, hi;
    asm("mov.b64 {%0, %1}, %2;" : "=f"(lo), "=f"(hi) : "l"(v));
    return make_float2(lo, hi);
}
__device__ __forceinline__ int i4(const int4 v, int z) {
    return z == 0 ? v.x : z == 1 ? v.y : z == 2 ? v.z : v.w;
}

// ---------------- unified GEMM ----------------
// C = A[M,K] @ B^T (B stored [N,K] if !BT, [K,N] if BT), f32x2 core, double-buffered.
// epil: 0 none, 1 leaky, 2 relu (scatter path); 3 = raw split-K partials, z = split idx.
// epil<3: z = parity index, per-z M/K/offsets/scatter params.
template<int BM, int BN, int TM, int TN, bool BT>
__global__ void __launch_bounds__(256, 2)
gemm_t(const float* __restrict__ A, const float* __restrict__ Bm,
       const float* __restrict__ bias, float* __restrict__ C,
       int4 Mz, int4 Kz, int4 Aoffz, int4 Boffz,
       int N, int lda, int ldb,
       int CO, int4 HWpz, int HWfull, int4 OWpz, int OWfull,
       int sy, int sx, int4 pyz, int4 pxz, int epil)
{
    constexpr int BK = 16;
    constexpr int NVA = (BM * BK) / (4 * 256);
    constexpr int NVB = (BN * BK) / (4 * 256);
    constexpr int TP = TM / 2;
    const int z = blockIdx.z;
    const int M = (epil == 3) ? Mz.x : i4(Mz, z);
    const int K = (epil == 3) ? Kz.x : i4(Kz, z);
    const int m0 = blockIdx.y * BM;
    if (m0 >= M) return;
    const int n0 = blockIdx.x * BN;
    const int LDA = (epil == 3) ? lda : K;
    const int LDB = BT ? ldb : ((epil == 3) ? ldb : K);
    const float* Ab = A + ((epil == 3) ? (size_t)z * K : (size_t)i4(Aoffz, z));
    const float* Bb = Bm + ((epil == 3) ? (BT ? (size_t)z * K * LDB : (size_t)z * K)
                                        : (size_t)i4(Boffz, z));

    __shared__ __align__(16) float As[2][BK][BM + 4];
    __shared__ __align__(16) float Bs[2][BK][BN + 4];
    const int tid = threadIdx.x;
    const int tx = tid & 15;    // M direction
    const int ty = tid >> 4;    // N direction
    const bool vecA = ((K & 15) == 0) && ((LDA & 3) == 0);
    const bool vecB = BT ? (((LDB & 3) == 0) && (n0 + BN <= N) && ((K & 15) == 0))
                         : (((K & 15) == 0) && ((LDB & 3) == 0));
    const int NT = (K + BK - 1) / BK;

    unsigned long long acc2[TP][TN];
#pragma unroll
    for (int p = 0; p < TP; p++)
#pragma unroll
        for (int j = 0; j < TN; j++) acc2[p][j] = 0ull;

    float4 ra[NVA], rb[NVB];

    auto load_tiles = [&](int t) {
        const int k0 = t * BK;
        // ---- A ----
        if (vecA) {
#pragma unroll
            for (int i = 0; i < NVA; i++) {
                int vid = tid + i * 256;
                int r = vid >> 2, kc = (vid & 3) << 2;
                int gm = m0 + r;
                ra[i] = (gm < M) ? *(const float4*)(Ab + (size_t)gm * LDA + k0 + kc)
                                 : make_float4(0.f, 0.f, 0.f, 0.f);
            }
        } else {
#pragma unroll
            for (int i = 0; i < NVA; i++) {
                int vid = tid + i * 256;
                int r = vid >> 2, kc = (vid & 3) << 2;
                int gm = m0 + r;
                float v[4];
#pragma unroll
                for (int j = 0; j < 4; j++) {
                    int gk = k0 + kc + j;
                    v[j] = (gm < M && gk < K) ? Ab[(size_t)gm * LDA + gk] : 0.f;
                }
                ra[i] = make_float4(v[0], v[1], v[2], v[3]);
            }
        }
        // ---- B ----
        if (!BT) {
            if (vecB) {
#pragma unroll
                for (int i = 0; i < NVB; i++) {
                    int vid = tid + i * 256;
                    int r = vid >> 2, kc = (vid & 3) << 2;
                    int gn = n0 + r;
                    rb[i] = (gn < N) ? *(const float4*)(Bb + (size_t)gn * LDB + k0 + kc)
                                     : make_float4(0.f, 0.f, 0.f, 0.f);
                }
            } else {
#pragma unroll
                for (int i = 0; i < NVB; i++) {
                    int vid = tid + i * 256;
                    int r = vid >> 2, kc = (vid & 3) << 2;
                    int gn = n0 + r;
                    float v[4];
#pragma unroll
                    for (int j = 0; j < 4; j++) {
                        int gk = k0 + kc + j;
                        v[j] = (gn < N && gk < K) ? Bb[(size_t)gn * LDB + gk] : 0.f;
                    }
                    rb[i] = make_float4(v[0], v[1], v[2], v[3]);
                }
            }
        } else {
            if (vecB) {
#pragma unroll
                for (int i = 0; i < NVB; i++) {
                    int vid = tid + i * 256;
                    int n4 = vid % (BN / 4), kc = vid / (BN / 4);
                    rb[i] = *(const float4*)(Bb + (size_t)(k0 + kc) * LDB + n0 + n4 * 4);
                }
            } else {
#pragma unroll
                for (int i = 0; i < NVB; i++) {
                    int vid = tid + i * 256;
                    int n4 = vid % (BN / 4), kc = vid / (BN / 4);
                    float v[4];
#pragma unroll
                    for (int j = 0; j < 4; j++) {
                        int gn = n0 + n4 * 4 + j, gk = k0 + kc;
                        v[j] = (gn < N && gk < K) ? Bb[(size_t)gk * LDB + gn] : 0.f;
                    }
                    rb[i] = make_float4(v[0], v[1], v[2], v[3]);
                }
            }
        }
    };
    auto store_tiles = [&](int buf) {
#pragma unroll
        for (int i = 0; i < NVA; i++) {
            int vid = tid + i * 256;
            int r = vid >> 2, kc = (vid & 3) << 2;
            As[buf][kc + 0][r] = ra[i].x;
            As[buf][kc + 1][r] = ra[i].y;
            As[buf][kc + 2][r] = ra[i].z;
            As[buf][kc + 3][r] = ra[i].w;
        }
        if (!BT) {
#pragma unroll
            for (int i = 0; i < NVB; i++) {
                int vid = tid + i * 256;
                int r = vid >> 2, kc = (vid & 3) << 2;
                Bs[buf][kc + 0][r] = rb[i].x;
                Bs[buf][kc + 1][r] = rb[i].y;
                Bs[buf][kc + 2][r] = rb[i].z;
                Bs[buf][kc + 3][r] = rb[i].w;
            }
        } else {
#pragma unroll
            for (int i = 0; i < NVB; i++) {
                int vid = tid + i * 256;
                int n4 = vid % (BN / 4), kc = vid / (BN / 4);
                *(float4*)&Bs[buf][kc][n4 * 4] = rb[i];
            }
        }
    };

    load_tiles(0);
    store_tiles(0);
    __syncthreads();

    for (int t = 0; t < NT; t++) {
        int cur = t & 1;
        if (t + 1 < NT) load_tiles(t + 1);
#pragma unroll
        for (int k = 0; k < BK; k++) {
            unsigned long long ap[TP];
#pragma unroll
            for (int g = 0; g < TM / 4; g++) {
                const ulonglong2 av = *(const ulonglong2*)&As[cur][k][g * 64 + tx * 4];
                ap[2 * g] = av.x; ap[2 * g + 1] = av.y;
            }
            unsigned long long bb[TN];
#pragma unroll
            for (int h = 0; h < TN / 4; h++) {
                const float4 b4 = *(const float4*)&Bs[cur][k][h * 64 + ty * 4];
                bb[4 * h + 0] = pack2(b4.x); bb[4 * h + 1] = pack2(b4.y);
                bb[4 * h + 2] = pack2(b4.z); bb[4 * h + 3] = pack2(b4.w);
            }
#pragma unroll
            for (int p = 0; p < TP; p++)
#pragma unroll
                for (int j = 0; j < TN; j++)
                    fma2(acc2[p][j], ap[p], bb[j]);
        }
        if (t + 1 < NT) store_tiles((t + 1) & 1);
        __syncthreads();
    }

    const int HWp = i4(HWpz, z), OWp = i4(OWpz, z), py = i4(pyz, z), px = i4(pxz, z);
#pragma unroll
    for (int p = 0; p < TP; p++) {
        float2 vv[TN];
#pragma unroll
        for (int j = 0; j < TN; j++) vv[j] = unpack2(acc2[p][j]);
#pragma unroll
        for (int e = 0; e < 2; e++) {
            int gm = m0 + (p >> 1) * 64 + (tx << 2) + ((p & 1) << 1) + e;
            if (gm >= M) continue;
            if (epil == 3) {
                float* Cp = C + ((size_t)z * M + gm) * N;
#pragma unroll
                for (int j = 0; j < TN; j++) {
                    int gn = n0 + (j >> 2) * 64 + (ty << 2) + (j & 3);
                    if (gn < N) Cp[gn] = e ? vv[j].y : vv[j].x;
                }
            } else {
                int bb2 = gm / HWp;
                int lhw = gm - bb2 * HWp;
                int ly = lhw / OWp, lx = lhw - ly * OWp;
                int hw = (py + sy * ly) * OWfull + (px + sx * lx);
                size_t base = ((size_t)bb2 * CO) * HWfull + hw;
#pragma unroll
                for (int j = 0; j < TN; j++) {
                    int gn = n0 + (j >> 2) * 64 + (ty << 2) + (j & 3);
                    if (gn >= N) continue;
                    float v = (e ? vv[j].y : vv[j].x) + bias[gn];
                    if (epil == 1) v = (v >= 0.f) ? v : 0.01f * v;
                    else if (epil == 2) v = fmaxf(v, 0.f);
                    C[base + (size_t)gn * HWfull] = v;
                }
            }
        }
    }
}

// ---------------- other kernels ----------------

__global__ void conv1_direct(const float* __restrict__ x, const float* __restrict__ w,
                             const float* __restrict__ bias, float* __restrict__ h1) {
    __shared__ float ws[1152];
    __shared__ float bs[128];
    for (int i = threadIdx.x; i < 1152; i += 256) ws[i] = w[i];
    for (int i = threadIdx.x; i < 128; i += 256) bs[i] = bias[i];
    __syncthreads();
    int b = blockIdx.y;
    int hw = blockIdx.x * 256 + threadIdx.x;
    int oy = hw >> 5, ox = hw & 31;
    float xv[9];
#pragma unroll
    for (int ky = 0; ky < 3; ky++)
#pragma unroll
        for (int kx = 0; kx < 3; kx++) {
            int iy = 2 * oy - 1 + ky, ix = 2 * ox - 1 + kx;
            xv[ky * 3 + kx] = (iy >= 0 && iy < 64 && ix >= 0 && ix < 64)
                                  ? x[(size_t)b * 4096 + iy * 64 + ix] : 0.f;
        }
    for (int co = 0; co < 128; co++) {
        float acc = bs[co];
        const float* wc = ws + co * 9;
#pragma unroll
        for (int t = 0; t < 9; t++) acc = fmaf(xv[t], wc[t], acc);
        acc = (acc >= 0.f) ? acc : 0.01f * acc;
        h1[((size_t)b * 128 + co) * 1024 + hw] = acc;
    }
}

__global__ void bn_stats(const float* __restrict__ h, float* mean, float* invstd,
                         int C, int Bn, int HW) {
    int c = blockIdx.x;
    float s = 0.f, ss = 0.f;
    for (int b = 0; b < Bn; b++) {
        const float* p = h + ((size_t)b * C + c) * HW;
        for (int i = threadIdx.x; i < HW; i += 512) {
            float v = p[i];
            s += v; ss += v * v;
        }
    }
    __shared__ float rs[512], rss[512];
    rs[threadIdx.x] = s; rss[threadIdx.x] = ss;
    __syncthreads();
    for (int st = 256; st > 0; st >>= 1) {
        if (threadIdx.x < st) { rs[threadIdx.x] += rs[threadIdx.x + st]; rss[threadIdx.x] += rss[threadIdx.x + st]; }
        __syncthreads();
    }
    if (threadIdx.x == 0) {
        float cnt = (float)Bn * (float)HW;
        float m = rs[0] / cnt;
        float var = rss[0] / cnt - m * m;
        mean[c] = m;
        invstd[c] = rsqrtf(var + 1e-5f);
    }
}

__global__ void fill_costab(float* tab) {
    int k = blockIdx.x * blockDim.x + threadIdx.x;
    if (k < 800) tab[k] = (float)cos(2.0 * 3.141592653589793238462643 * (double)k / 800.0);
}

__global__ void im2colF(const float* __restrict__ in, const float* __restrict__ mean,
                        const float* __restrict__ invstd, float* __restrict__ col,
                        int CI, int IH, int IW, int OH, int OW, int s, int p) {
    int row = blockIdx.x;
    int kk  = blockIdx.y * blockDim.x + threadIdx.x;
    int K = CI * 9;
    if (kk >= K) return;
    int OHW = OH * OW;
    int b = row / OHW, hw = row % OHW;
    int oy = hw / OW, ox = hw % OW;
    int ci = kk / 9, r = kk % 9, ky = r / 3, kx = r % 3;
    int iy = oy * s - p + ky, ix = ox * s - p + kx;
    float v = 0.f;
    if (iy >= 0 && iy < IH && ix >= 0 && ix < IW) {
        v = in[(((size_t)b * CI + ci) * IH + iy) * IW + ix];
        v = (v - mean[ci]) * invstd[ci];
    }
    col[(size_t)row * K + kk] = v;
}

// batched parity im2col for stride-2 transposed convs (zero-free), z = parity
__global__ void im2colPb(const float* __restrict__ in, float* __restrict__ col,
                         int CI, int IH, int IW, int pd,
                         int4 Ktz, int4 Rowsz, int4 cOffz, int4 HWpz, int4 OWpz,
                         int4 pyz, int4 pxz, int4 ky0z, int4 nkxz) {
    int z = blockIdx.z;
    int Kt = i4(Ktz, z);
    int rows = i4(Rowsz, z);
    int row = blockIdx.x;
    if (row >= rows) return;
    int kk = blockIdx.y * 256 + threadIdx.x;
    if (kk >= Kt) return;
    int HWp = i4(HWpz, z), OWp = i4(OWpz, z);
    int py = i4(pyz, z), px = i4(pxz, z);
    int ky0 = i4(ky0z, z), nkx = i4(nkxz, z);
    int b = row / HWp, r = row % HWp;
    int ly = r / OWp, lx = r % OWp;
    int oy = py + 2 * ly, ox = px + 2 * lx;
    int kx0 = ((pd - px) % 2 + 2) % 2;
    int nt_ci = kk / nkx;         // ci*nky + jy  (nt = nky*nkx)
    int jx = kk - nt_ci * nkx;
    int nky = 2 - ky0;
    int ci = nt_ci / nky, jy = nt_ci - ci * nky;
    int ky = ky0 + 2 * jy, kx = kx0 + 2 * jx;
    int tyy = oy + ky - pd, txx = ox + kx - pd;   // even by construction
    float v = 0.f;
    if (tyy >= 0 && txx >= 0) {
        int iy = tyy >> 1, ix = txx >> 1;
        if (iy < IH && ix < IW)
            v = in[(((size_t)b * CI + ci) * IH + iy) * IW + ix];
    }
    col[(size_t)i4(cOffz, z) + (size_t)row * Kt + kk] = v;
}

// batched parity weight transform, z = parity
__global__ void wt_convT_b(const float* __restrict__ w, float* __restrict__ wt,
                           int CI, int CO, int pd,
                           int4 wOffz, int4 ky0z, int4 kx0z, int4 nkyz, int4 nkxz) {
    int z = blockIdx.z;
    int nky = i4(nkyz, z), nkx = i4(nkxz, z);
    int nt = nky * nkx;
    int idx = blockIdx.x * 256 + threadIdx.x;
    if (idx >= CO * CI * nt) return;
    int ky0 = i4(ky0z, z), kx0 = i4(kx0z, z);
    int co = idx / (CI * nt);
    int r = idx % (CI * nt);
    int ci = r / nt, rr = r % nt;
    int jy = rr / nkx, jx = rr % nkx;
    int ky = ky0 + 2 * jy, kx = kx0 + 2 * jx;
    wt[i4(wOffz, z) + idx] = w[(((size_t)ci * CO + co) * 3 + (2 - ky)) * 3 + (2 - kx)];
}

__global__ void norm_inplace(float* h, const float* __restrict__ mean,
                             const float* __restrict__ invstd, int C, int HW, int total) {
    int idx = blockIdx.x * blockDim.x + threadIdx.x;
    if (idx >= total) return;
    int c = (idx / HW) % C;
    h[idx] = (h[idx] - mean[c]) * invstd[c];
}

// split-K reduce for fc: sum partials, +bias, relu
__global__ void reduce_fc(const float* __restrict__ part, const float* __restrict__ bias,
                          float* __restrict__ out, int M, int N, int S) {
    int idx = blockIdx.x * blockDim.x + threadIdx.x;
    if (idx >= M * N) return;
    int m = idx / N, n = idx - m * N;
    float s = 0.f;
    for (int z = 0; z < S; z++) s += part[((size_t)z * M + m) * N + n];
    s += bias[n];
    out[idx] = fmaxf(s, 0.f);
}

// split-K reduce for conv4: +bias, leaky, scatter to NCHW h4
__global__ void reduce_conv4(const float* __restrict__ part, const float* __restrict__ bias,
                             float* __restrict__ h4o) {
    int idx = blockIdx.x * 256 + threadIdx.x;
    if (idx >= 1600 * 1024) return;
    int m = idx >> 10, c = idx & 1023;
    float s = 0.f;
#pragma unroll
    for (int z = 0; z < 4; z++) s += part[((size_t)z * 1600 + m) * 1024 + c];
    s += bias[c];
    s = (s >= 0.f) ? s : 0.01f * s;
    int b = m >> 4, hw = m & 15;
    h4o[((size_t)b * 1024 + c) * 16 + hw] = s;
}

__global__ void compute_R(const float* __restrict__ eig, const float* __restrict__ tab,
                          float* __restrict__ R) {
    int b = blockIdx.x;
    __shared__ float s[800];
    __shared__ float t[800];
    for (int i = threadIdx.x; i < 800; i += 256) { s[i] = eig[b * 800 + i]; t[i] = tab[i]; }
    __syncthreads();
    for (int o = threadIdx.x; o < 800; o += 256) {
        int m = o >> 3, l = o & 7;
        float acc = 0.f;
        for (int q = 0; q < 800; q++) {
            int mp = q >> 3, lp = q & 7;
            int ph = (8 * m * mp + 100 * l * lp) % 800;
            acc += s[q] * t[ph];
        }
        R[b * 800 + o] = acc;
    }
}

__global__ void write_C(const float* __restrict__ R, float* __restrict__ C) {
    int b = blockIdx.y;
    int i = blockIdx.x;
    __shared__ float r[800];
    const float inv = 0.035355339059327376f;
    for (int q = threadIdx.x; q < 800; q += 256) r[q] = R[b * 800 + q] * inv;
    __syncthreads();
    size_t base = ((size_t)b * 800 + i) * 800;
    for (int j = threadIdx.x; j < 800; j += 256)
        C[base + j] = r[(i - j + 800) % 800];
}

__global__ void ct5_conv(const float* __restrict__ t4, const float* __restrict__ w,
                         const float* __restrict__ bias, float* __restrict__ out) {
    __shared__ float ws[576];
    for (int i = threadIdx.x; i < 576; i += blockDim.x) {
        int ci = i / 9, rr = i % 9, ky = rr / 3, kx = rr % 3;
        ws[i] = w[ci * 9 + (2 - ky) * 3 + (2 - kx)];
    }
    __syncthreads();
    int b = blockIdx.y;
    int o = blockIdx.x * blockDim.x + threadIdx.x;
    if (o >= 2401) return;
    int oy = o / 49, ox = o % 49;
    float acc = bias[0];
    for (int ci = 0; ci < 64; ci++) {
        const float* p = t4 + ((size_t)b * 64 + ci) * 47 * 47;
        const float* wc = ws + ci * 9;
#pragma unroll
        for (int ky = 0; ky < 3; ky++) {
            int iy = oy + ky - 2;
            if (iy < 0 || iy >= 47) continue;
#pragma unroll
            for (int kx = 0; kx < 3; kx++) {
                int ix = ox + kx - 2;
                if (ix < 0 || ix >= 47) continue;
                acc += p[iy * 47 + ix] * wc[ky * 3 + kx];
            }
        }
    }
    out[(size_t)b * 2401 + o] = acc;
}

// ---------------- host side ----------------

static float* symaddr(const void* s) {
    void* p = nullptr;
    cudaGetSymbolAddress(&p, s);
    return (float*)p;
}

static const int4 Z0 = {0, 0, 0, 0};
static int4 all4(int v) { return make_int4(v, v, v, v); }

// plain (single-z) GEMM launch helpers
static void gemm_plain(int variant, const float* A, const float* Bm, const float* bias,
                       float* C, int M, int N, int K,
                       int CO, int HWp, int HWfull, int OWp, int OWfull, int epil) {
    int4 Mz = all4(M), Kz = all4(K);
    if (variant == 0) {  // 128x128
        dim3 g((N + 127) / 128, (M + 127) / 128, 1);
        gemm_t<128, 128, 8, 8, false><<<g, 256>>>(A, Bm, bias, C, Mz, Kz, Z0, Z0,
            N, K, K, CO, all4(HWp), HWfull, all4(OWp), OWfull, 1, 1, Z0, Z0, epil);
    } else {             // 64x64
        dim3 g((N + 63) / 64, (M + 63) / 64, 1);
        gemm_t<64, 64, 4, 4, false><<<g, 256>>>(A, Bm, bias, C, Mz, Kz, Z0, Z0,
            N, K, K, CO, all4(HWp), HWfull, all4(OWp), OWfull, 1, 1, Z0, Z0, epil);
    }
}

struct ParMeta {
    int4 Mz, Kz, cOff, wOff, HWpz, OWpz, pyz, pxz, ky0z, kx0z, nkyz, nkxz, Rowsz;
    int maxM, maxKt;
};

static ParMeta parity_meta(int B, int CI, int OH, int OW, int pd, int CO) {
    ParMeta m{};
    int Mv[4], Kv[4], co[4], wo[4], hwp[4], owp[4], pyv[4], pxv[4], ky0v[4], kx0v[4],
        nkyv[4], nkxv[4];
    int cacc = 0, wacc = 0, i = 0;
    m.maxM = 0; m.maxKt = 0;
    for (int py = 0; py < 2; py++)
        for (int px = 0; px < 2; px++, i++) {
            int ky0 = ((pd - py) % 2 + 2) % 2, nky = 2 - ky0;
            int kx0 = ((pd - px) % 2 + 2) % 2, nkx = 2 - kx0;
            int OHp = (OH - py + 1) / 2, OWp = (OW - px + 1) / 2;
            int Kt = CI * nky * nkx;
            int Mp = B * OHp * OWp;
            Mv[i] = Mp; Kv[i] = Kt; co[i] = cacc; wo[i] = wacc;
            hwp[i] = OHp * OWp; owp[i] = OWp;
            pyv[i] = py; pxv[i] = px; ky0v[i] = ky0; kx0v[i] = kx0;
            nkyv[i] = nky; nkxv[i] = nkx;
            cacc += Mp * Kt; wacc += CO * Kt;
            if (Mp > m.maxM) m.maxM = Mp;
            if (Kt > m.maxKt) m.maxKt = Kt;
        }
    m.Mz = make_int4(Mv[0], Mv[1], Mv[2], Mv[3]);
    m.Kz = make_int4(Kv[0], Kv[1], Kv[2], Kv[3]);
    m.cOff = make_int4(co[0], co[1], co[2], co[3]);
    m.wOff = make_int4(wo[0], wo[1], wo[2], wo[3]);
    m.HWpz = make_int4(hwp[0], hwp[1], hwp[2], hwp[3]);
    m.OWpz = make_int4(owp[0], owp[1], owp[2], owp[3]);
    m.pyz = make_int4(pyv[0], pyv[1], pyv[2], pyv[3]);
    m.pxz = make_int4(pxv[0], pxv[1], pxv[2], pxv[3]);
    m.ky0z = make_int4(ky0v[0], ky0v[1], ky0v[2], ky0v[3]);
    m.kx0z = make_int4(kx0v[0], kx0v[1], kx0v[2], kx0v[3]);
    m.nkyz = make_int4(nkyv[0], nkyv[1], nkyv[2], nkyv[3]);
    m.nkxz = make_int4(nkxv[0], nkxv[1], nkxv[2], nkxv[3]);
    m.Rowsz = m.Mz;
    return m;
}

// variant: 0 = 128x128, 1 = 64x64, 2 = 128x64
static void convT_layer(int variant, const float* in, const float* w, const float* bias,
                        float* outp, int B, int CI, int CO,
                        int IH, int IW, int OH, int OW, int pd) {
    float* col = symaddr(g_col);
    float* wT  = symaddr(g_wT);
    ParMeta m = parity_meta(B, CI, OH, OW, pd, CO);

    wt_convT_b<<<dim3((CO * CI * 4 + 255) / 256, 1, 4), 256>>>(
        w, wT, CI, CO, pd, m.wOff, m.ky0z, m.kx0z, m.nkyz, m.nkxz);
    im2colPb<<<dim3(m.maxM, (m.maxKt + 255) / 256, 4), 256>>>(
        in, col, CI, IH, IW, pd, m.Kz, m.Rowsz, m.cOff, m.HWpz, m.OWpz,
        m.pyz, m.pxz, m.ky0z, m.nkxz);

    if (variant == 0) {
        dim3 g((CO + 127) / 128, (m.maxM + 127) / 128, 4);
        gemm_t<128, 128, 8, 8, false><<<g, 256>>>(col, wT, bias, outp,
            m.Mz, m.Kz, m.cOff, m.wOff, CO, 0, 0,
            CO, m.HWpz, OH * OW, m.OWpz, OW, 2, 2, m.pyz, m.pxz, 0);
    } else if (variant == 1) {
        dim3 g((CO + 63) / 64, (m.maxM + 63) / 64, 4);
        gemm_t<64, 64, 4, 4, false><<<g, 256>>>(col, wT, bias, outp,
            m.Mz, m.Kz, m.cOff, m.wOff, CO, 0, 0,
            CO, m.HWpz, OH * OW, m.OWpz, OW, 2, 2, m.pyz, m.pxz, 0);
    } else {
        dim3 g((CO + 63) / 64, (m.maxM + 127) / 128, 4);
        gemm_t<128, 64, 8, 4, false><<<g, 256>>>(col, wT, bias, outp,
            m.Mz, m.Kz, m.cOff, m.wOff, CO, 0, 0,
            CO, m.HWpz, OH * OW, m.OWpz, OW, 2, 2, m.pyz, m.pxz, 0);
    }
}

static void run_im2colF(const float* in, const float* mean, const float* invstd, float* col,
                        int B, int CI, int IH, int IW, int OH, int OW, int s, int p) {
    dim3 g(B * OH * OW, (CI * 9 + 255) / 256);
    im2colF<<<g, 256>>>(in, mean, invstd, col, CI, IH, IW, OH, OW, s, p);
}

extern "C" void kernel_launch(void* const* d_in, const int* in_sizes, int n_in,
                              void* d_out, int out_size) {
    const float* x       = (const float*)d_in[0];
    const float* conv1_w = (const float*)d_in[1];
    const float* conv1_b = (const float*)d_in[2];
    const float* conv2_w = (const float*)d_in[3];
    const float* conv2_b = (const float*)d_in[4];
    const float* conv3_w = (const float*)d_in[5];
    const float* conv3_b = (const float*)d_in[6];
    const float* conv4_w = (const float*)d_in[7];
    const float* conv4_b = (const float*)d_in[8];
    const float* fc_w    = (const float*)d_in[9];
    const float* fc_b    = (const float*)d_in[10];
    const float* dec_w   = (const float*)d_in[11];
    const float* dec_b   = (const float*)d_in[12];
    const float* ct1_w   = (const float*)d_in[13];
    const float* ct1_b   = (const float*)d_in[14];
    const float* ct2_w   = (const float*)d_in[15];
    const float* ct2_b   = (const float*)d_in[16];
    const float* ct3_w   = (const float*)d_in[17];
    const float* ct3_b   = (const float*)d_in[18];
    const float* ct4_w   = (const float*)d_in[19];
    const float* ct4_b   = (const float*)d_in[20];
    const float* ct5_w   = (const float*)d_in[21];
    const float* ct5_b   = (const float*)d_in[22];

    float* out = (float*)d_out;
    float* out_d   = out;                        // 100*49*49
    float* out_C   = out + 240100;               // 100*800*800
    float* out_eig = out + 240100 + 64000000;    // 100*800

    float* col  = symaddr(g_col);
    float* h1   = symaddr(g_h1);
    float* h2   = symaddr(g_h2);
    float* h3   = symaddr(g_h3);
    float* h4   = symaddr(g_h4);
    float* part = symaddr(g_part);
    float* R    = symaddr(g_R);
    float* tab  = symaddr(g_tab);
    float* mean = symaddr(g_mean);
    float* ivs  = symaddr(g_invstd);
    float* d0   = symaddr(g_d0);
    float* t1   = symaddr(g_t1);
    float* t2   = symaddr(g_t2);
    float* t3   = symaddr(g_t3);
    float* t4   = symaddr(g_t4);

    const int B = 100;

    // ---- encoder ----
    conv1_direct<<<dim3(4, B), 256>>>(x, conv1_w, conv1_b, h1);                 // 1
    bn_stats<<<128, 512>>>(h1, mean, ivs, 128, B, 1024);                        // 2

    // conv2: 128 -> 256, 32 -> 16
    run_im2colF(h1, mean, ivs, col, B, 128, 32, 32, 16, 16, 2, 1);              // 3
    gemm_plain(0, col, conv2_w, conv2_b, h2, B * 256, 256, 1152,
               256, 256, 256, 16, 16, 1);                                       // 4 (profiled)
    bn_stats<<<256, 512>>>(h2, mean, ivs, 256, B, 256);

    // conv3: 256 -> 1024, 16 -> 8
    run_im2colF(h2, mean, ivs, col, B, 256, 16, 16, 8, 8, 2, 1);
    gemm_plain(0, col, conv3_w, conv3_b, h3, B * 64, 1024, 2304,
               1024, 64, 64, 8, 8, 1);
    bn_stats<<<1024, 512>>>(h3, mean, ivs, 1024, B, 64);

    // conv4: 1024 -> 1024, 8 -> 4 : split-K=4 with 128x128 tiles
    run_im2colF(h3, mean, ivs, col, B, 1024, 8, 8, 4, 4, 2, 1);
    {
        dim3 g((1024 + 127) / 128, (1600 + 127) / 128, 4);
        gemm_t<128, 128, 8, 8, false><<<g, 256>>>(col, conv4_w, conv4_b, part,
            all4(1600), all4(2304), Z0, Z0, 1024, 9216, 9216,
            1024, all4(1), 1, all4(1), 1, 1, 1, Z0, Z0, 3);
    }
    reduce_conv4<<<(1600 * 1024 + 255) / 256, 256>>>(part, conv4_b, h4);
    bn_stats<<<1024, 512>>>(h4, mean, ivs, 1024, B, 16);
    norm_inplace<<<(1638400 + 255) / 256, 256>>>(h4, mean, ivs, 1024, 16, 1638400);

    // fc: (100,16384) @ fc_w[16384,800] (BT), split-K=8
    {
        dim3 g((800 + 63) / 64, (100 + 63) / 64, 8);
        gemm_t<64, 64, 4, 4, true><<<g, 256>>>(h4, fc_w, fc_b, part,
            all4(100), all4(2048), Z0, Z0, 800, 16384, 800,
            800, all4(1), 1, all4(1), 1, 1, 1, Z0, Z0, 3);
    }
    reduce_fc<<<(80000 + 255) / 256, 256>>>(part, fc_b, out_eig, 100, 800, 8);

    // ---- spectral part ----
    fill_costab<<<4, 256>>>(tab);
    compute_R<<<B, 256>>>(out_eig, tab, R);
    write_C<<<dim3(800, B), 256>>>(R, out_C);

    // dec: (100,800) @ dec_w[800,9216] (BT) -> d0
    {
        dim3 g((9216 + 63) / 64, (100 + 63) / 64, 1);
        gemm_t<64, 64, 4, 4, true><<<g, 256>>>(R, dec_w, dec_b, d0,
            all4(100), all4(800), Z0, Z0, 9216, 800, 9216,
            9216, all4(1), 1, all4(1), 1, 1, 1, Z0, Z0, 0);
    }

    // ---- decoder: batched parity-decomposed transposed convs ----
    convT_layer(1, d0, ct1_w, ct1_b, t1, B, 1024, 512, 3, 3, 5, 5, 1);
    convT_layer(1, t1, ct2_w, ct2_b, t2, B, 512, 256, 5, 5, 11, 11, 2);
    convT_layer(0, t2, ct3_w, ct3_b, t3, B, 256, 128, 11, 11, 23, 23, 2);
    convT_layer(2, t3, ct4_w, ct4_b, t4, B, 128, 64, 23, 23, 47, 47, 2);

    // ct5: direct conv 64 -> 1, 47 -> 49
    ct5_conv<<<dim3((2401 + 255) / 256, B), 256>>>(t4, ct5_w, ct5_b, out_d);
}

// round 5
// speedup vs baseline: 3.5640x; 1.0006x over previous
#include <cuda_runtime.h>
#include <math.h>

// ---------------- scratch (__device__ globals) ----------------
__device__ float g_col[66000000];   // batched parity im2col (ct4 total 64.5M) / conv2 29.5M
__device__ float g_wT[13200000];    // per-layer parity weight slices (<= 9*CO*CI)
__device__ float g_h1[13107200];    // 100x128x32x32
__device__ float g_h2[6553600];     // 100x256x16x16
__device__ float g_h3[6553600];     // 100x1024x8x8
__device__ float g_h4[1638400];     // 100x1024x4x4
__device__ float g_part[6553600];   // split-K partials: conv4 4x1600x1024, fc 8x100x800
__device__ float g_R[80000];
__device__ float g_tab[800];
__device__ float g_mean[1024];
__device__ float g_invstd[1024];
__device__ float g_d0[921600];      // 100x1024x3x3
__device__ float g_t1[1280000];     // 100x512x5x5
__device__ float g_t2[3097600];     // 100x256x11x11
__device__ float g_t3[6771200];     // 100x128x23x23
__device__ float g_t4[14137600];    // 100x64x47x47

// ---------------- packed f32x2 helpers ----------------
__device__ __forceinline__ unsigned long long pack2(float v) {
    unsigned long long r;
    asm("mov.b64 %0, {%1, %1};" : "=l"(r) : "f"(v));
    return r;
}
__device__ __forceinline__ void fma2(unsigned long long& acc, unsigned long long a,
                                     unsigned long long b) {
    asm("fma.rn.f32x2 %0, %1, %2, %0;" : "+l"(acc) : "l"(a), "l"(b));
}
__device__ __forceinline__ float2 unpack2(unsigned long long v) {
    float lo, hi;
    asm("mov.b64 {%0, %1}, %2;" : "=f"(lo), "=f"(hi) : "l"(v));
    return make_float2(lo, hi);
}
__device__ __forceinline__ int i4(const int4 v, int z) {
    return z == 0 ? v.x : z == 1 ? v.y : z == 2 ? v.z : v.w;
}

// ---------------- unified GEMM ----------------
// C = A[M,K] @ B^T (B stored [N,K] if !BT, [K,N] if BT), f32x2 core, double-buffered.
// epil: 0 none, 1 leaky, 2 relu (scatter path); 3 = raw split-K partials, z = split idx.
// epil<3: z = parity index, per-z M/K/offsets/scatter params.
template<int BM, int BN, int TM, int TN, bool BT>
__global__ void __launch_bounds__(256, 2)
gemm_t(const float* __restrict__ A, const float* __restrict__ Bm,
       const float* __restrict__ bias, float* __restrict__ C,
       int4 Mz, int4 Kz, int4 Aoffz, int4 Boffz,
       int N, int lda, int ldb,
       int CO, int4 HWpz, int HWfull, int4 OWpz, int OWfull,
       int sy, int sx, int4 pyz, int4 pxz, int epil)
{
    constexpr int BK = 16;
    constexpr int NVA = (BM * BK) / (4 * 256);
    constexpr int NVB = (BN * BK) / (4 * 256);
    constexpr int TP = TM / 2;
    const int z = blockIdx.z;
    const int M = (epil == 3) ? Mz.x : i4(Mz, z);
    const int K = (epil == 3) ? Kz.x : i4(Kz, z);
    const int m0 = blockIdx.y * BM;
    if (m0 >= M) return;
    const int n0 = blockIdx.x * BN;
    const int LDA = (epil == 3) ? lda : K;
    const int LDB = BT ? ldb : ((epil == 3) ? ldb : K);
    const float* Ab = A + ((epil == 3) ? (size_t)z * K : (size_t)i4(Aoffz, z));
    const float* Bb = Bm + ((epil == 3) ? (BT ? (size_t)z * K * LDB : (size_t)z * K)
                                        : (size_t)i4(Boffz, z));

    __shared__ __align__(16) float As[2][BK][BM + 4];
    __shared__ __align__(16) float Bs[2][BK][BN + 4];
    const int tid = threadIdx.x;
    const int tx = tid & 15;    // M direction
    const int ty = tid >> 4;    // N direction
    const bool vecA = ((K & 15) == 0) && ((LDA & 3) == 0);
    const bool vecB = BT ? (((LDB & 3) == 0) && (n0 + BN <= N) && ((K & 15) == 0))
                         : (((K & 15) == 0) && ((LDB & 3) == 0));
    const int NT = (K + BK - 1) / BK;

    unsigned long long acc2[TP][TN];
#pragma unroll
    for (int p = 0; p < TP; p++)
#pragma unroll
        for (int j = 0; j < TN; j++) acc2[p][j] = 0ull;

    float4 ra[NVA], rb[NVB];

    auto load_tiles = [&](int t) {
        const int k0 = t * BK;
        // ---- A ----
        if (vecA) {
#pragma unroll
            for (int i = 0; i < NVA; i++) {
                int vid = tid + i * 256;
                int r = vid >> 2, kc = (vid & 3) << 2;
                int gm = m0 + r;
                ra[i] = (gm < M) ? *(const float4*)(Ab + (size_t)gm * LDA + k0 + kc)
                                 : make_float4(0.f, 0.f, 0.f, 0.f);
            }
        } else {
#pragma unroll
            for (int i = 0; i < NVA; i++) {
                int vid = tid + i * 256;
                int r = vid >> 2, kc = (vid & 3) << 2;
                int gm = m0 + r;
                float v[4];
#pragma unroll
                for (int j = 0; j < 4; j++) {
                    int gk = k0 + kc + j;
                    v[j] = (gm < M && gk < K) ? Ab[(size_t)gm * LDA + gk] : 0.f;
                }
                ra[i] = make_float4(v[0], v[1], v[2], v[3]);
            }
        }
        // ---- B ----
        if (!BT) {
            if (vecB) {
#pragma unroll
                for (int i = 0; i < NVB; i++) {
                    int vid = tid + i * 256;
                    int r = vid >> 2, kc = (vid & 3) << 2;
                    int gn = n0 + r;
                    rb[i] = (gn < N) ? *(const float4*)(Bb + (size_t)gn * LDB + k0 + kc)
                                     : make_float4(0.f, 0.f, 0.f, 0.f);
                }
            } else {
#pragma unroll
                for (int i = 0; i < NVB; i++) {
                    int vid = tid + i * 256;
                    int r = vid >> 2, kc = (vid & 3) << 2;
                    int gn = n0 + r;
                    float v[4];
#pragma unroll
                    for (int j = 0; j < 4; j++) {
                        int gk = k0 + kc + j;
                        v[j] = (gn < N && gk < K) ? Bb[(size_t)gn * LDB + gk] : 0.f;
                    }
                    rb[i] = make_float4(v[0], v[1], v[2], v[3]);
                }
            }
        } else {
            if (vecB) {
#pragma unroll
                for (int i = 0; i < NVB; i++) {
                    int vid = tid + i * 256;
                    int n4 = vid % (BN / 4), kc = vid / (BN / 4);
                    rb[i] = *(const float4*)(Bb + (size_t)(k0 + kc) * LDB + n0 + n4 * 4);
                }
            } else {
#pragma unroll
                for (int i = 0; i < NVB; i++) {
                    int vid = tid + i * 256;
                    int n4 = vid % (BN / 4), kc = vid / (BN / 4);
                    float v[4];
#pragma unroll
                    for (int j = 0; j < 4; j++) {
                        int gn = n0 + n4 * 4 + j, gk = k0 + kc;
                        v[j] = (gn < N && gk < K) ? Bb[(size_t)gk * LDB + gn] : 0.f;
                    }
                    rb[i] = make_float4(v[0], v[1], v[2], v[3]);
                }
            }
        }
    };
    auto store_tiles = [&](int buf) {
#pragma unroll
        for (int i = 0; i < NVA; i++) {
            int vid = tid + i * 256;
            int r = vid >> 2, kc = (vid & 3) << 2;
            As[buf][kc + 0][r] = ra[i].x;
            As[buf][kc + 1][r] = ra[i].y;
            As[buf][kc + 2][r] = ra[i].z;
            As[buf][kc + 3][r] = ra[i].w;
        }
        if (!BT) {
#pragma unroll
            for (int i = 0; i < NVB; i++) {
                int vid = tid + i * 256;
                int r = vid >> 2, kc = (vid & 3) << 2;
                Bs[buf][kc + 0][r] = rb[i].x;
                Bs[buf][kc + 1][r] = rb[i].y;
                Bs[buf][kc + 2][r] = rb[i].z;
                Bs[buf][kc + 3][r] = rb[i].w;
            }
        } else {
#pragma unroll
            for (int i = 0; i < NVB; i++) {
                int vid = tid + i * 256;
                int n4 = vid % (BN / 4), kc = vid / (BN / 4);
                *(float4*)&Bs[buf][kc][n4 * 4] = rb[i];
            }
        }
    };

    load_tiles(0);
    store_tiles(0);
    __syncthreads();

    for (int t = 0; t < NT; t++) {
        int cur = t & 1;
        if (t + 1 < NT) load_tiles(t + 1);
#pragma unroll
        for (int k = 0; k < BK; k++) {
            unsigned long long ap[TP];
#pragma unroll
            for (int g = 0; g < TM / 4; g++) {
                const ulonglong2 av = *(const ulonglong2*)&As[cur][k][g * 64 + tx * 4];
                ap[2 * g] = av.x; ap[2 * g + 1] = av.y;
            }
            unsigned long long bb[TN];
#pragma unroll
            for (int h = 0; h < TN / 4; h++) {
                const float4 b4 = *(const float4*)&Bs[cur][k][h * 64 + ty * 4];
                bb[4 * h + 0] = pack2(b4.x); bb[4 * h + 1] = pack2(b4.y);
                bb[4 * h + 2] = pack2(b4.z); bb[4 * h + 3] = pack2(b4.w);
            }
#pragma unroll
            for (int p = 0; p < TP; p++)
#pragma unroll
                for (int j = 0; j < TN; j++)
                    fma2(acc2[p][j], ap[p], bb[j]);
        }
        if (t + 1 < NT) store_tiles((t + 1) & 1);
        __syncthreads();
    }

    const int HWp = i4(HWpz, z), OWp = i4(OWpz, z), py = i4(pyz, z), px = i4(pxz, z);
#pragma unroll
    for (int p = 0; p < TP; p++) {
        float2 vv[TN];
#pragma unroll
        for (int j = 0; j < TN; j++) vv[j] = unpack2(acc2[p][j]);
#pragma unroll
        for (int e = 0; e < 2; e++) {
            int gm = m0 + (p >> 1) * 64 + (tx << 2) + ((p & 1) << 1) + e;
            if (gm >= M) continue;
            if (epil == 3) {
                float* Cp = C + ((size_t)z * M + gm) * N;
#pragma unroll
                for (int j = 0; j < TN; j++) {
                    int gn = n0 + (j >> 2) * 64 + (ty << 2) + (j & 3);
                    if (gn < N) Cp[gn] = e ? vv[j].y : vv[j].x;
                }
            } else {
                int bb2 = gm / HWp;
                int lhw = gm - bb2 * HWp;
                int ly = lhw / OWp, lx = lhw - ly * OWp;
                int hw = (py + sy * ly) * OWfull + (px + sx * lx);
                size_t base = ((size_t)bb2 * CO) * HWfull + hw;
#pragma unroll
                for (int j = 0; j < TN; j++) {
                    int gn = n0 + (j >> 2) * 64 + (ty << 2) + (j & 3);
                    if (gn >= N) continue;
                    float v = (e ? vv[j].y : vv[j].x) + bias[gn];
                    if (epil == 1) v = (v >= 0.f) ? v : 0.01f * v;
                    else if (epil == 2) v = fmaxf(v, 0.f);
                    C[base + (size_t)gn * HWfull] = v;
                }
            }
        }
    }
}

// ---------------- other kernels ----------------

__global__ void conv1_direct(const float* __restrict__ x, const float* __restrict__ w,
                             const float* __restrict__ bias, float* __restrict__ h1) {
    __shared__ float ws[1152];
    __shared__ float bs[128];
    for (int i = threadIdx.x; i < 1152; i += 256) ws[i] = w[i];
    for (int i = threadIdx.x; i < 128; i += 256) bs[i] = bias[i];
    __syncthreads();
    int b = blockIdx.y;
    int hw = blockIdx.x * 256 + threadIdx.x;
    int oy = hw >> 5, ox = hw & 31;
    float xv[9];
#pragma unroll
    for (int ky = 0; ky < 3; ky++)
#pragma unroll
        for (int kx = 0; kx < 3; kx++) {
            int iy = 2 * oy - 1 + ky, ix = 2 * ox - 1 + kx;
            xv[ky * 3 + kx] = (iy >= 0 && iy < 64 && ix >= 0 && ix < 64)
                                  ? x[(size_t)b * 4096 + iy * 64 + ix] : 0.f;
        }
    for (int co = 0; co < 128; co++) {
        float acc = bs[co];
        const float* wc = ws + co * 9;
#pragma unroll
        for (int t = 0; t < 9; t++) acc = fmaf(xv[t], wc[t], acc);
        acc = (acc >= 0.f) ? acc : 0.01f * acc;
        h1[((size_t)b * 128 + co) * 1024 + hw] = acc;
    }
}

__global__ void bn_stats(const float* __restrict__ h, float* mean, float* invstd,
                         int C, int Bn, int HW) {
    int c = blockIdx.x;
    float s = 0.f, ss = 0.f;
    for (int b = 0; b < Bn; b++) {
        const float* p = h + ((size_t)b * C + c) * HW;
        for (int i = threadIdx.x; i < HW; i += 512) {
            float v = p[i];
            s += v; ss += v * v;
        }
    }
    __shared__ float rs[512], rss[512];
    rs[threadIdx.x] = s; rss[threadIdx.x] = ss;
    __syncthreads();
    for (int st = 256; st > 0; st >>= 1) {
        if (threadIdx.x < st) { rs[threadIdx.x] += rs[threadIdx.x + st]; rss[threadIdx.x] += rss[threadIdx.x + st]; }
        __syncthreads();
    }
    if (threadIdx.x == 0) {
        float cnt = (float)Bn * (float)HW;
        float m = rs[0] / cnt;
        float var = rss[0] / cnt - m * m;
        mean[c] = m;
        invstd[c] = rsqrtf(var + 1e-5f);
    }
}

__global__ void fill_costab(float* tab) {
    int k = blockIdx.x * blockDim.x + threadIdx.x;
    if (k < 800) tab[k] = (float)cos(2.0 * 3.141592653589793238462643 * (double)k / 800.0);
}

__global__ void im2colF(const float* __restrict__ in, const float* __restrict__ mean,
                        const float* __restrict__ invstd, float* __restrict__ col,
                        int CI, int IH, int IW, int OH, int OW, int s, int p) {
    int row = blockIdx.x;
    int kk  = blockIdx.y * blockDim.x + threadIdx.x;
    int K = CI * 9;
    if (kk >= K) return;
    int OHW = OH * OW;
    int b = row / OHW, hw = row % OHW;
    int oy = hw / OW, ox = hw % OW;
    int ci = kk / 9, r = kk % 9, ky = r / 3, kx = r % 3;
    int iy = oy * s - p + ky, ix = ox * s - p + kx;
    float v = 0.f;
    if (iy >= 0 && iy < IH && ix >= 0 && ix < IW) {
        v = in[(((size_t)b * CI + ci) * IH + iy) * IW + ix];
        v = (v - mean[ci]) * invstd[ci];
    }
    col[(size_t)row * K + kk] = v;
}

// batched parity im2col for stride-2 transposed convs (zero-free), z = parity
__global__ void im2colPb(const float* __restrict__ in, float* __restrict__ col,
                         int CI, int IH, int IW, int pd,
                         int4 Ktz, int4 Rowsz, int4 cOffz, int4 HWpz, int4 OWpz,
                         int4 pyz, int4 pxz, int4 ky0z, int4 nkxz) {
    int z = blockIdx.z;
    int Kt = i4(Ktz, z);
    int rows = i4(Rowsz, z);
    int row = blockIdx.x;
    if (row >= rows) return;
    int kk = blockIdx.y * 256 + threadIdx.x;
    if (kk >= Kt) return;
    int HWp = i4(HWpz, z), OWp = i4(OWpz, z);
    int py = i4(pyz, z), px = i4(pxz, z);
    int ky0 = i4(ky0z, z), nkx = i4(nkxz, z);
    int b = row / HWp, r = row % HWp;
    int ly = r / OWp, lx = r % OWp;
    int oy = py + 2 * ly, ox = px + 2 * lx;
    int kx0 = ((pd - px) % 2 + 2) % 2;
    int nt_ci = kk / nkx;         // ci*nky + jy  (nt = nky*nkx)
    int jx = kk - nt_ci * nkx;
    int nky = 2 - ky0;
    int ci = nt_ci / nky, jy = nt_ci - ci * nky;
    int ky = ky0 + 2 * jy, kx = kx0 + 2 * jx;
    int tyy = oy + ky - pd, txx = ox + kx - pd;   // even by construction
    float v = 0.f;
    if (tyy >= 0 && txx >= 0) {
        int iy = tyy >> 1, ix = txx >> 1;
        if (iy < IH && ix < IW)
            v = in[(((size_t)b * CI + ci) * IH + iy) * IW + ix];
    }
    col[(size_t)i4(cOffz, z) + (size_t)row * Kt + kk] = v;
}

// batched parity weight transform, z = parity
__global__ void wt_convT_b(const float* __restrict__ w, float* __restrict__ wt,
                           int CI, int CO, int pd,
                           int4 wOffz, int4 ky0z, int4 kx0z, int4 nkyz, int4 nkxz) {
    int z = blockIdx.z;
    int nky = i4(nkyz, z), nkx = i4(nkxz, z);
    int nt = nky * nkx;
    int idx = blockIdx.x * 256 + threadIdx.x;
    if (idx >= CO * CI * nt) return;
    int ky0 = i4(ky0z, z), kx0 = i4(kx0z, z);
    int co = idx / (CI * nt);
    int r = idx % (CI * nt);
    int ci = r / nt, rr = r % nt;
    int jy = rr / nkx, jx = rr % nkx;
    int ky = ky0 + 2 * jy, kx = kx0 + 2 * jx;
    wt[i4(wOffz, z) + idx] = w[(((size_t)ci * CO + co) * 3 + (2 - ky)) * 3 + (2 - kx)];
}

__global__ void norm_inplace(float* h, const float* __restrict__ mean,
                             const float* __restrict__ invstd, int C, int HW, int total) {
    int idx = blockIdx.x * blockDim.x + threadIdx.x;
    if (idx >= total) return;
    int c = (idx / HW) % C;
    h[idx] = (h[idx] - mean[c]) * invstd[c];
}

// split-K reduce for fc: sum partials, +bias, relu
__global__ void reduce_fc(const float* __restrict__ part, const float* __restrict__ bias,
                          float* __restrict__ out, int M, int N, int S) {
    int idx = blockIdx.x * blockDim.x + threadIdx.x;
    if (idx >= M * N) return;
    int m = idx / N, n = idx - m * N;
    float s = 0.f;
    for (int z = 0; z < S; z++) s += part[((size_t)z * M + m) * N + n];
    s += bias[n];
    out[idx] = fmaxf(s, 0.f);
}

// split-K reduce for conv4: +bias, leaky, scatter to NCHW h4
__global__ void reduce_conv4(const float* __restrict__ part, const float* __restrict__ bias,
                             float* __restrict__ h4o) {
    int idx = blockIdx.x * 256 + threadIdx.x;
    if (idx >= 1600 * 1024) return;
    int m = idx >> 10, c = idx & 1023;
    float s = 0.f;
#pragma unroll
    for (int z = 0; z < 4; z++) s += part[((size_t)z * 1600 + m) * 1024 + c];
    s += bias[c];
    s = (s >= 0.f) ? s : 0.01f * s;
    int b = m >> 4, hw = m & 15;
    h4o[((size_t)b * 1024 + c) * 16 + hw] = s;
}

__global__ void compute_R(const float* __restrict__ eig, const float* __restrict__ tab,
                          float* __restrict__ R) {
    int b = blockIdx.x;
    __shared__ float s[800];
    __shared__ float t[800];
    for (int i = threadIdx.x; i < 800; i += 256) { s[i] = eig[b * 800 + i]; t[i] = tab[i]; }
    __syncthreads();
    for (int o = threadIdx.x; o < 800; o += 256) {
        int m = o >> 3, l = o & 7;
        float acc = 0.f;
        for (int q = 0; q < 800; q++) {
            int mp = q >> 3, lp = q & 7;
            int ph = (8 * m * mp + 100 * l * lp) % 800;
            acc += s[q] * t[ph];
        }
        R[b * 800 + o] = acc;
    }
}

__global__ void write_C(const float* __restrict__ R, float* __restrict__ C) {
    int b = blockIdx.y;
    int i = blockIdx.x;
    __shared__ float r[800];
    const float inv = 0.035355339059327376f;
    for (int q = threadIdx.x; q < 800; q += 256) r[q] = R[b * 800 + q] * inv;
    __syncthreads();
    size_t base = ((size_t)b * 800 + i) * 800;
    for (int j = threadIdx.x; j < 800; j += 256)
        C[base + j] = r[(i - j + 800) % 800];
}

__global__ void ct5_conv(const float* __restrict__ t4, const float* __restrict__ w,
                         const float* __restrict__ bias, float* __restrict__ out) {
    __shared__ float ws[576];
    for (int i = threadIdx.x; i < 576; i += blockDim.x) {
        int ci = i / 9, rr = i % 9, ky = rr / 3, kx = rr % 3;
        ws[i] = w[ci * 9 + (2 - ky) * 3 + (2 - kx)];
    }
    __syncthreads();
    int b = blockIdx.y;
    int o = blockIdx.x * blockDim.x + threadIdx.x;
    if (o >= 2401) return;
    int oy = o / 49, ox = o % 49;
    float acc = bias[0];
    for (int ci = 0; ci < 64; ci++) {
        const float* p = t4 + ((size_t)b * 64 + ci) * 47 * 47;
        const float* wc = ws + ci * 9;
#pragma unroll
        for (int ky = 0; ky < 3; ky++) {
            int iy = oy + ky - 2;
            if (iy < 0 || iy >= 47) continue;
#pragma unroll
            for (int kx = 0; kx < 3; kx++) {
                int ix = ox + kx - 2;
                if (ix < 0 || ix >= 47) continue;
                acc += p[iy * 47 + ix] * wc[ky * 3 + kx];
            }
        }
    }
    out[(size_t)b * 2401 + o] = acc;
}

// ---------------- host side ----------------

static float* symaddr(const void* s) {
    void* p = nullptr;
    cudaGetSymbolAddress(&p, s);
    return (float*)p;
}

static const int4 Z0 = {0, 0, 0, 0};
static int4 all4(int v) { return make_int4(v, v, v, v); }

// plain (single-z) GEMM launch helpers
static void gemm_plain(int variant, const float* A, const float* Bm, const float* bias,
                       float* C, int M, int N, int K,
                       int CO, int HWp, int HWfull, int OWp, int OWfull, int epil) {
    int4 Mz = all4(M), Kz = all4(K);
    if (variant == 0) {  // 128x128
        dim3 g((N + 127) / 128, (M + 127) / 128, 1);
        gemm_t<128, 128, 8, 8, false><<<g, 256>>>(A, Bm, bias, C, Mz, Kz, Z0, Z0,
            N, K, K, CO, all4(HWp), HWfull, all4(OWp), OWfull, 1, 1, Z0, Z0, epil);
    } else {             // 64x64
        dim3 g((N + 63) / 64, (M + 63) / 64, 1);
        gemm_t<64, 64, 4, 4, false><<<g, 256>>>(A, Bm, bias, C, Mz, Kz, Z0, Z0,
            N, K, K, CO, all4(HWp), HWfull, all4(OWp), OWfull, 1, 1, Z0, Z0, epil);
    }
}

struct ParMeta {
    int4 Mz, Kz, cOff, wOff, HWpz, OWpz, pyz, pxz, ky0z, kx0z, nkyz, nkxz, Rowsz;
    int maxM, maxKt;
};

static ParMeta parity_meta(int B, int CI, int OH, int OW, int pd, int CO) {
    ParMeta m{};
    int Mv[4], Kv[4], co[4], wo[4], hwp[4], owp[4], pyv[4], pxv[4], ky0v[4], kx0v[4],
        nkyv[4], nkxv[4];
    int cacc = 0, wacc = 0, i = 0;
    m.maxM = 0; m.maxKt = 0;
    for (int py = 0; py < 2; py++)
        for (int px = 0; px < 2; px++, i++) {
            int ky0 = ((pd - py) % 2 + 2) % 2, nky = 2 - ky0;
            int kx0 = ((pd - px) % 2 + 2) % 2, nkx = 2 - kx0;
            int OHp = (OH - py + 1) / 2, OWp = (OW - px + 1) / 2;
            int Kt = CI * nky * nkx;
            int Mp = B * OHp * OWp;
            Mv[i] = Mp; Kv[i] = Kt; co[i] = cacc; wo[i] = wacc;
            hwp[i] = OHp * OWp; owp[i] = OWp;
            pyv[i] = py; pxv[i] = px; ky0v[i] = ky0; kx0v[i] = kx0;
            nkyv[i] = nky; nkxv[i] = nkx;
            cacc += Mp * Kt; wacc += CO * Kt;
            if (Mp > m.maxM) m.maxM = Mp;
            if (Kt > m.maxKt) m.maxKt = Kt;
        }
    m.Mz = make_int4(Mv[0], Mv[1], Mv[2], Mv[3]);
    m.Kz = make_int4(Kv[0], Kv[1], Kv[2], Kv[3]);
    m.cOff = make_int4(co[0], co[1], co[2], co[3]);
    m.wOff = make_int4(wo[0], wo[1], wo[2], wo[3]);
    m.HWpz = make_int4(hwp[0], hwp[1], hwp[2], hwp[3]);
    m.OWpz = make_int4(owp[0], owp[1], owp[2], owp[3]);
    m.pyz = make_int4(pyv[0], pyv[1], pyv[2], pyv[3]);
    m.pxz = make_int4(pxv[0], pxv[1], pxv[2], pxv[3]);
    m.ky0z = make_int4(ky0v[0], ky0v[1], ky0v[2], ky0v[3]);
    m.kx0z = make_int4(kx0v[0], kx0v[1], kx0v[2], kx0v[3]);
    m.nkyz = make_int4(nkyv[0], nkyv[1], nkyv[2], nkyv[3]);
    m.nkxz = make_int4(nkxv[0], nkxv[1], nkxv[2], nkxv[3]);
    m.Rowsz = m.Mz;
    return m;
}

// variant: 0 = 128x128, 1 = 64x64, 2 = 128x64
static void convT_layer(int variant, const float* in, const float* w, const float* bias,
                        float* outp, int B, int CI, int CO,
                        int IH, int IW, int OH, int OW, int pd) {
    float* col = symaddr(g_col);
    float* wT  = symaddr(g_wT);
    ParMeta m = parity_meta(B, CI, OH, OW, pd, CO);

    wt_convT_b<<<dim3((CO * CI * 4 + 255) / 256, 1, 4), 256>>>(
        w, wT, CI, CO, pd, m.wOff, m.ky0z, m.kx0z, m.nkyz, m.nkxz);
    im2colPb<<<dim3(m.maxM, (m.maxKt + 255) / 256, 4), 256>>>(
        in, col, CI, IH, IW, pd, m.Kz, m.Rowsz, m.cOff, m.HWpz, m.OWpz,
        m.pyz, m.pxz, m.ky0z, m.nkxz);

    if (variant == 0) {
        dim3 g((CO + 127) / 128, (m.maxM + 127) / 128, 4);
        gemm_t<128, 128, 8, 8, false><<<g, 256>>>(col, wT, bias, outp,
            m.Mz, m.Kz, m.cOff, m.wOff, CO, 0, 0,
            CO, m.HWpz, OH * OW, m.OWpz, OW, 2, 2, m.pyz, m.pxz, 0);
    } else if (variant == 1) {
        dim3 g((CO + 63) / 64, (m.maxM + 63) / 64, 4);
        gemm_t<64, 64, 4, 4, false><<<g, 256>>>(col, wT, bias, outp,
            m.Mz, m.Kz, m.cOff, m.wOff, CO, 0, 0,
            CO, m.HWpz, OH * OW, m.OWpz, OW, 2, 2, m.pyz, m.pxz, 0);
    } else {
        dim3 g((CO + 63) / 64, (m.maxM + 127) / 128, 4);
        gemm_t<128, 64, 8, 4, false><<<g, 256>>>(col, wT, bias, outp,
            m.Mz, m.Kz, m.cOff, m.wOff, CO, 0, 0,
            CO, m.HWpz, OH * OW, m.OWpz, OW, 2, 2, m.pyz, m.pxz, 0);
    }
}

static void run_im2colF(const float* in, const float* mean, const float* invstd, float* col,
                        int B, int CI, int IH, int IW, int OH, int OW, int s, int p) {
    dim3 g(B * OH * OW, (CI * 9 + 255) / 256);
    im2colF<<<g, 256>>>(in, mean, invstd, col, CI, IH, IW, OH, OW, s, p);
}

extern "C" void kernel_launch(void* const* d_in, const int* in_sizes, int n_in,
                              void* d_out, int out_size) {
    const float* x       = (const float*)d_in[0];
    const float* conv1_w = (const float*)d_in[1];
    const float* conv1_b = (const float*)d_in[2];
    const float* conv2_w = (const float*)d_in[3];
    const float* conv2_b = (const float*)d_in[4];
    const float* conv3_w = (const float*)d_in[5];
    const float* conv3_b = (const float*)d_in[6];
    const float* conv4_w = (const float*)d_in[7];
    const float* conv4_b = (const float*)d_in[8];
    const float* fc_w    = (const float*)d_in[9];
    const float* fc_b    = (const float*)d_in[10];
    const float* dec_w   = (const float*)d_in[11];
    const float* dec_b   = (const float*)d_in[12];
    const float* ct1_w   = (const float*)d_in[13];
    const float* ct1_b   = (const float*)d_in[14];
    const float* ct2_w   = (const float*)d_in[15];
    const float* ct2_b   = (const float*)d_in[16];
    const float* ct3_w   = (const float*)d_in[17];
    const float* ct3_b   = (const float*)d_in[18];
    const float* ct4_w   = (const float*)d_in[19];
    const float* ct4_b   = (const float*)d_in[20];
    const float* ct5_w   = (const float*)d_in[21];
    const float* ct5_b   = (const float*)d_in[22];

    float* out = (float*)d_out;
    float* out_d   = out;                        // 100*49*49
    float* out_C   = out + 240100;               // 100*800*800
    float* out_eig = out + 240100 + 64000000;    // 100*800

    float* col  = symaddr(g_col);
    float* h1   = symaddr(g_h1);
    float* h2   = symaddr(g_h2);
    float* h3   = symaddr(g_h3);
    float* h4   = symaddr(g_h4);
    float* part = symaddr(g_part);
    float* R    = symaddr(g_R);
    float* tab  = symaddr(g_tab);
    float* mean = symaddr(g_mean);
    float* ivs  = symaddr(g_invstd);
    float* d0   = symaddr(g_d0);
    float* t1   = symaddr(g_t1);
    float* t2   = symaddr(g_t2);
    float* t3   = symaddr(g_t3);
    float* t4   = symaddr(g_t4);

    const int B = 100;

    // ---- encoder ----
    conv1_direct<<<dim3(4, B), 256>>>(x, conv1_w, conv1_b, h1);                 // 1
    bn_stats<<<128, 512>>>(h1, mean, ivs, 128, B, 1024);                        // 2

    // conv2: 128 -> 256, 32 -> 16
    run_im2colF(h1, mean, ivs, col, B, 128, 32, 32, 16, 16, 2, 1);              // 3
    gemm_plain(0, col, conv2_w, conv2_b, h2, B * 256, 256, 1152,
               256, 256, 256, 16, 16, 1);                                       // 4 (profiled)
    bn_stats<<<256, 512>>>(h2, mean, ivs, 256, B, 256);

    // conv3: 256 -> 1024, 16 -> 8
    run_im2colF(h2, mean, ivs, col, B, 256, 16, 16, 8, 8, 2, 1);
    gemm_plain(0, col, conv3_w, conv3_b, h3, B * 64, 1024, 2304,
               1024, 64, 64, 8, 8, 1);
    bn_stats<<<1024, 512>>>(h3, mean, ivs, 1024, B, 64);

    // conv4: 1024 -> 1024, 8 -> 4 : split-K=4 with 128x128 tiles
    run_im2colF(h3, mean, ivs, col, B, 1024, 8, 8, 4, 4, 2, 1);
    {
        dim3 g((1024 + 127) / 128, (1600 + 127) / 128, 4);
        gemm_t<128, 128, 8, 8, false><<<g, 256>>>(col, conv4_w, conv4_b, part,
            all4(1600), all4(2304), Z0, Z0, 1024, 9216, 9216,
            1024, all4(1), 1, all4(1), 1, 1, 1, Z0, Z0, 3);
    }
    reduce_conv4<<<(1600 * 1024 + 255) / 256, 256>>>(part, conv4_b, h4);
    bn_stats<<<1024, 512>>>(h4, mean, ivs, 1024, B, 16);
    norm_inplace<<<(1638400 + 255) / 256, 256>>>(h4, mean, ivs, 1024, 16, 1638400);

    // fc: (100,16384) @ fc_w[16384,800] (BT), split-K=8
    {
        dim3 g((800 + 63) / 64, (100 + 63) / 64, 8);
        gemm_t<64, 64, 4, 4, true><<<g, 256>>>(h4, fc_w, fc_b, part,
            all4(100), all4(2048), Z0, Z0, 800, 16384, 800,
            800, all4(1), 1, all4(1), 1, 1, 1, Z0, Z0, 3);
    }
    reduce_fc<<<(80000 + 255) / 256, 256>>>(part, fc_b, out_eig, 100, 800, 8);

    // ---- spectral part ----
    fill_costab<<<4, 256>>>(tab);
    compute_R<<<B, 256>>>(out_eig, tab, R);
    write_C<<<dim3(800, B), 256>>>(R, out_C);

    // dec: (100,800) @ dec_w[800,9216] (BT) -> d0
    {
        dim3 g((9216 + 63) / 64, (100 + 63) / 64, 1);
        gemm_t<64, 64, 4, 4, true><<<g, 256>>>(R, dec_w, dec_b, d0,
            all4(100), all4(800), Z0, Z0, 9216, 800, 9216,
            9216, all4(1), 1, all4(1), 1, 1, 1, Z0, Z0, 0);
    }

    // ---- decoder: batched parity-decomposed transposed convs ----
    convT_layer(1, d0, ct1_w, ct1_b, t1, B, 1024, 512, 3, 3, 5, 5, 1);
    convT_layer(1, t1, ct2_w, ct2_b, t2, B, 512, 256, 5, 5, 11, 11, 2);
    convT_layer(0, t2, ct3_w, ct3_b, t3, B, 256, 128, 11, 11, 23, 23, 2);
    convT_layer(2, t3, ct4_w, ct4_b, t4, B, 128, 64, 23, 23, 47, 47, 2);

    // ct5: direct conv 64 -> 1, 47 -> 49
    ct5_conv<<<dim3((2401 + 255) / 256, B), 256>>>(t4, ct5_w, ct5_b, out_d);
}

// round 6
// speedup vs baseline: 4.5381x; 1.2733x over previous
#include <cuda_runtime.h>

// ---------------- scratch ----------------
__device__ __align__(16) float g_wT[13200000];
__device__ __align__(16) float g_bias[9216];
__device__ __align__(16) float g_h1[13107200];   // 100x32x32x128 NHWC
__device__ __align__(16) float g_h2[6553600];    // 100x16x16x256
__device__ __align__(16) float g_h3[6553600];    // 100x8x8x1024
__device__ __align__(16) float g_h4[1638400];    // 100x4x4x1024
__device__ __align__(16) float g_part[6553600];
__device__ __align__(16) float g_R[80000];
__device__ __align__(16) float g_tab[800];
__device__ float g_mean[1024];
__device__ float g_invstd[1024];
__device__ float g_bnsum[1024];
__device__ float g_bnss[1024];
__device__ __align__(16) float g_d0[921600];     // 100x3x3x1024 NHWC
__device__ __align__(16) float g_t1[1280000];    // 100x5x5x512
__device__ __align__(16) float g_t2[3097600];    // 100x11x11x256
__device__ __align__(16) float g_t3[6771200];    // 100x23x23x128
__device__ __align__(16) float g_t4[14137600];   // 100x47x47x64

// ---------------- f32x2 ----------------
__device__ __forceinline__ unsigned long long pack2(float v) {
    unsigned long long r; asm("mov.b64 %0, {%1, %1};" : "=l"(r) : "f"(v)); return r;
}
__device__ __forceinline__ void fma2(unsigned long long& a, unsigned long long x,
                                     unsigned long long y) {
    asm("fma.rn.f32x2 %0, %1, %2, %0;" : "+l"(a) : "l"(x), "l"(y));
}
__device__ __forceinline__ float2 unpack2(unsigned long long v) {
    float lo, hi; asm("mov.b64 {%0, %1}, %2;" : "=f"(lo), "=f"(hi) : "l"(v));
    return make_float2(lo, hi);
}
__device__ __forceinline__ int i4(const int4 v, int z) {
    return z == 0 ? v.x : z == 1 ? v.y : z == 2 ? v.z : v.w;
}

// ---------------- unified implicit GEMM ----------------
// AM: 0 plain A[M,K](lda); 1 fwd-conv NHWC gather; 2 parity-convT NHWC gather
// EP: 0 C[gm*N+gn]+bias+act; 1 raw split-K partial; 3 parity NHWC image store
struct GP {
    const float *A, *B, *bias; float* C;
    int M, N, K, lda, ldb;
    int CI, IH, IW, OW, OHW, s, pp, pd;
    int4 Mz, Kz, wOffz, HWpz, OWpz, pyz, pxz, ky0z, kx0z, nkxz;
    int OHfull, OWfull, CO, act;
};

template<int BM, int BN, int TM, int TN, int AM, int EP>
__global__ void __launch_bounds__(256, 2) gemm_u(GP p)
{
    constexpr int BK = 16;
    constexpr int NVA = (BM * BK) / 1024;
    constexpr int NVB = (BN * BK) / 1024;
    constexpr int TP = TM / 2;
    const int tid = threadIdx.x, tx = tid & 15, ty = tid >> 4;
    const int z = blockIdx.z;
    const int M = (AM == 2) ? i4(p.Mz, z) : p.M;
    const int K = (AM == 2) ? i4(p.Kz, z) : p.K;
    const int m0 = blockIdx.y * BM;
    if (m0 >= M) return;
    const int n0 = blockIdx.x * BN;
    const int koff = (EP == 1) ? z * K : 0;
    int HWp = 0, OWp = 0, py = 0, px = 0, ky0 = 0, kx0 = 0, nkx = 1;
    if (AM == 2) {
        HWp = i4(p.HWpz, z); OWp = i4(p.OWpz, z); py = i4(p.pyz, z); px = i4(p.pxz, z);
        ky0 = i4(p.ky0z, z); kx0 = i4(p.kx0z, z); nkx = i4(p.nkxz, z);
    }
    const float* Bb = p.B + ((AM == 2) ? (size_t)i4(p.wOffz, z) : 0);

    int abase[NVA ? NVA : 1], aoy[NVA ? NVA : 1], aox[NVA ? NVA : 1];
    if (AM >= 1) {
#pragma unroll
        for (int i = 0; i < NVA; i++) {
            int r = (tid >> 2) + 64 * i;
            int gm = m0 + r;
            bool ok = gm < M;
            int g = ok ? gm : 0;
            if (AM == 1) {
                int b = g / p.OHW, hw = g - b * p.OHW;
                int oy = hw / p.OW, ox = hw - oy * p.OW;
                aoy[i] = ok ? (oy * p.s - p.pp) : -1000000;
                aox[i] = ox * p.s - p.pp;
                abase[i] = b * p.IH * p.IW * p.CI;
            } else {
                int b = g / HWp, rr = g - b * HWp;
                int ly = rr / OWp, lx = rr - ly * OWp;
                aoy[i] = ok ? (py + 2 * ly - p.pd) : -1000000;
                aox[i] = px + 2 * lx - p.pd;
                abase[i] = b * p.IH * p.IW * p.CI;
            }
        }
    }

    __shared__ __align__(16) float As[2][BK][BM + 4];
    __shared__ __align__(16) float Bs[2][BK][BN + 4];
    const int NT = K / BK;
    float4 ra[NVA], rb[NVB];
    const bool vecB = ((p.ldb & 3) == 0) && (n0 + BN <= p.N);
    const bool vecA = ((p.lda & 3) == 0);

    auto loadA = [&](int t) {
        const int k0 = koff + t * BK;
        if (AM == 0) {
#pragma unroll
            for (int i = 0; i < NVA; i++) {
                int vid = tid + i * 256;
                int r = vid >> 2, kc = (vid & 3) << 2;
                int gm = m0 + r;
                if (vecA) {
                    ra[i] = (gm < M) ? *(const float4*)(p.A + (size_t)gm * p.lda + k0 + kc)
                                     : make_float4(0.f, 0.f, 0.f, 0.f);
                } else {
                    float v[4];
#pragma unroll
                    for (int j = 0; j < 4; j++)
                        v[j] = (gm < M) ? p.A[(size_t)gm * p.lda + k0 + kc + j] : 0.f;
                    ra[i] = make_float4(v[0], v[1], v[2], v[3]);
                }
            }
        } else if (AM == 1) {
            int tap = k0 / p.CI;
            int cb = k0 - tap * p.CI + ((tid & 3) << 2);
            int ky = tap / 3, kx = tap - 3 * ky;
#pragma unroll
            for (int i = 0; i < NVA; i++) {
                int iy = aoy[i] + ky, ix = aox[i] + kx;
                bool v = ((unsigned)iy < (unsigned)p.IH) & ((unsigned)ix < (unsigned)p.IW);
                float4 tmp = make_float4(0.f, 0.f, 0.f, 0.f);
                if (v) tmp = *(const float4*)(p.A + (size_t)abase[i] +
                                              (size_t)(iy * p.IW + ix) * p.CI + cb);
                ra[i] = tmp;
            }
        } else {
            int tt = k0 / p.CI;
            int cb = k0 - tt * p.CI + ((tid & 3) << 2);
            int jy, jx;
            if (nkx == 2) { jy = tt >> 1; jx = tt & 1; } else { jy = tt; jx = 0; }
            int ky = ky0 + 2 * jy, kx = kx0 + 2 * jx;
#pragma unroll
            for (int i = 0; i < NVA; i++) {
                int tyy = aoy[i] + ky, txx = aox[i] + kx;
                int iy = tyy >> 1, ix = txx >> 1;
                bool v = (tyy >= 0) & (txx >= 0) & (iy < p.IH) & (ix < p.IW);
                float4 tmp = make_float4(0.f, 0.f, 0.f, 0.f);
                if (v) tmp = *(const float4*)(p.A + (size_t)abase[i] +
                                              (size_t)(iy * p.IW + ix) * p.CI + cb);
                ra[i] = tmp;
            }
        }
    };
    auto loadB = [&](int t) {
        const int k0 = koff + t * BK;
#pragma unroll
        for (int i = 0; i < NVB; i++) {
            int vid = tid + i * 256;
            int n4 = vid % (BN / 4), kc = vid / (BN / 4);
            if (vecB) {
                rb[i] = *(const float4*)(Bb + (size_t)(k0 + kc) * p.ldb + n0 + n4 * 4);
            } else {
                float v[4];
#pragma unroll
                for (int j = 0; j < 4; j++) {
                    int gn = n0 + n4 * 4 + j;
                    v[j] = (gn < p.N) ? Bb[(size_t)(k0 + kc) * p.ldb + gn] : 0.f;
                }
                rb[i] = make_float4(v[0], v[1], v[2], v[3]);
            }
        }
    };
    auto storeT = [&](int buf) {
#pragma unroll
        for (int i = 0; i < NVA; i++) {
            int vid = tid + i * 256;
            int r = vid >> 2, kc = (vid & 3) << 2;
            As[buf][kc + 0][r] = ra[i].x;
            As[buf][kc + 1][r] = ra[i].y;
            As[buf][kc + 2][r] = ra[i].z;
            As[buf][kc + 3][r] = ra[i].w;
        }
#pragma unroll
        for (int i = 0; i < NVB; i++) {
            int vid = tid + i * 256;
            int n4 = vid % (BN / 4), kc = vid / (BN / 4);
            *(float4*)&Bs[buf][kc][n4 * 4] = rb[i];
        }
    };

    unsigned long long acc2[TP][TN];
#pragma unroll
    for (int q = 0; q < TP; q++)
#pragma unroll
        for (int j = 0; j < TN; j++) acc2[q][j] = 0ull;

    loadA(0); loadB(0);
    storeT(0);
    __syncthreads();

    for (int t = 0; t < NT; t++) {
        int cur = t & 1;
        if (t + 1 < NT) { loadA(t + 1); loadB(t + 1); }
#pragma unroll
        for (int k = 0; k < BK; k++) {
            unsigned long long ap[TP];
#pragma unroll
            for (int g = 0; g < TM / 4; g++) {
                const ulonglong2 av = *(const ulonglong2*)&As[cur][k][g * 64 + tx * 4];
                ap[2 * g] = av.x; ap[2 * g + 1] = av.y;
            }
            unsigned long long bb[TN];
#pragma unroll
            for (int h = 0; h < TN / 4; h++) {
                const float4 b4 = *(const float4*)&Bs[cur][k][h * 64 + ty * 4];
                bb[4 * h + 0] = pack2(b4.x); bb[4 * h + 1] = pack2(b4.y);
                bb[4 * h + 2] = pack2(b4.z); bb[4 * h + 3] = pack2(b4.w);
            }
#pragma unroll
            for (int q = 0; q < TP; q++)
#pragma unroll
                for (int j = 0; j < TN; j++)
                    fma2(acc2[q][j], ap[q], bb[j]);
        }
        if (t + 1 < NT) storeT((t + 1) & 1);
        __syncthreads();
    }

#pragma unroll
    for (int q = 0; q < TP; q++) {
        float2 vv[TN];
#pragma unroll
        for (int j = 0; j < TN; j++) vv[j] = unpack2(acc2[q][j]);
#pragma unroll
        for (int e = 0; e < 2; e++) {
            int gm = m0 + (q >> 1) * 64 + (tx << 2) + ((q & 1) << 1) + e;
            if (gm >= M) continue;
            if (EP == 1) {
                float* Cp = p.C + ((size_t)z * p.M + gm) * p.N;
#pragma unroll
                for (int j = 0; j < TN; j++) {
                    int gn = n0 + (j >> 2) * 64 + (ty << 2) + (j & 3);
                    if (gn < p.N) Cp[gn] = e ? vv[j].y : vv[j].x;
                }
            } else {
                size_t base;
                if (EP == 0) base = (size_t)gm * p.N;
                else {
                    int b = gm / HWp, rr = gm - b * HWp;
                    int ly = rr / OWp, lx = rr - ly * OWp;
                    int oy = py + 2 * ly, ox = px + 2 * lx;
                    base = (((size_t)b * p.OHfull + oy) * p.OWfull + ox) * (size_t)p.CO;
                }
#pragma unroll
                for (int j = 0; j < TN; j++) {
                    int gn = n0 + (j >> 2) * 64 + (ty << 2) + (j & 3);
                    if (gn < p.N) {
                        float v = (e ? vv[j].y : vv[j].x) + p.bias[gn];
                        if (p.act == 1) v = (v >= 0.f) ? v : 0.01f * v;
                        else if (p.act == 2) v = fmaxf(v, 0.f);
                        p.C[base + gn] = v;
                    }
                }
            }
        }
    }
}

// ---------------- aux kernels ----------------

__global__ void conv1_nhwc(const float* __restrict__ x, const float* __restrict__ w,
                           const float* __restrict__ b, float* __restrict__ h1) {
    int pix = blockIdx.x, img = blockIdx.y, co = threadIdx.x;
    int oy = pix >> 5, ox = pix & 31;
    __shared__ float xv[9];
    if (co < 9) {
        int ky = co / 3, kx = co % 3;
        int iy = 2 * oy - 1 + ky, ix = 2 * ox - 1 + kx;
        xv[co] = ((unsigned)iy < 64u && (unsigned)ix < 64u)
                     ? x[(size_t)img * 4096 + iy * 64 + ix] : 0.f;
    }
    __syncthreads();
    float acc = b[co];
#pragma unroll
    for (int t = 0; t < 9; t++) acc = fmaf(xv[t], w[co * 9 + t], acc);
    acc = (acc >= 0.f) ? acc : 0.01f * acc;
    h1[((size_t)img * 1024 + pix) * 128 + co] = acc;
}

__global__ void bn_zero_k() {
    int i = blockIdx.x * 256 + threadIdx.x;
    if (i < 1024) { g_bnsum[i] = 0.f; g_bnss[i] = 0.f; }
}
__global__ void bn_part(const float* __restrict__ h, int C, long total) {
    long stride = (long)gridDim.x * 256;
    long e = (long)blockIdx.x * 256 + threadIdx.x;
    if (e >= total) return;
    int c = (int)(e % C);
    float s = 0.f, ss = 0.f;
    for (; e < total; e += stride) { float v = h[e]; s += v; ss += v * v; }
    atomicAdd(&g_bnsum[c], s);
    atomicAdd(&g_bnss[c], ss);
}
__global__ void bn_fin(float* mean, float* ivs, int C, float cnt) {
    int c = blockIdx.x * 256 + threadIdx.x;
    if (c < C) {
        float m = g_bnsum[c] / cnt;
        float var = g_bnss[c] / cnt - m * m;
        mean[c] = m;
        ivs[c] = rsqrtf(var + 1e-5f);
    }
}
__global__ void norm_k(float* h, const float* __restrict__ mean,
                       const float* __restrict__ ivs, int C, long total) {
    long stride = (long)gridDim.x * 256;
    for (long e = (long)blockIdx.x * 256 + threadIdx.x; e < total; e += stride) {
        int c = (int)(e % C);
        h[e] = (h[e] - mean[c]) * ivs[c];
    }
}

// fwd conv weight -> [k=tap*CI+ci][co]
__global__ void wt_fwd(const float* __restrict__ w, float* __restrict__ wt, int CI, int CO) {
    int idx = blockIdx.x * 256 + threadIdx.x;
    if (idx >= 9 * CI * CO) return;
    int k = idx / CO, co = idx - k * CO;
    int ci = k % CI, tap = k / CI;
    wt[idx] = w[((size_t)co * CI + ci) * 9 + tap];
}

// parity convT weight -> wt[wOff + (tt*CI+ci)*CO + co]
__global__ void wt_par(const float* __restrict__ w, float* __restrict__ wt,
                       int CI, int CO, int4 Ktz, int4 wOffz, int4 ky0z, int4 kx0z, int4 nkxz) {
    int z = blockIdx.z;
    int Kt = i4(Ktz, z);
    int idx = blockIdx.x * 256 + threadIdx.x;
    if (idx >= Kt * CO) return;
    int k = idx / CO, co = idx - k * CO;
    int ci = k % CI, tt = k / CI;
    int nkx = i4(nkxz, z);
    int jy, jx;
    if (nkx == 2) { jy = tt >> 1; jx = tt & 1; } else { jy = tt; jx = 0; }
    int ky = i4(ky0z, z) + 2 * jy, kx = i4(kx0z, z) + 2 * jx;
    wt[i4(wOffz, z) + idx] = w[(((size_t)ci * CO + co) * 3 + (2 - ky)) * 3 + (2 - kx)];
}

__global__ void perm_fc(const float* __restrict__ w, float* __restrict__ o) {
    int idx = blockIdx.x * 256 + threadIdx.x;
    if (idx >= 16384 * 800) return;
    int k = idx / 800, n = idx - k * 800;
    int hw = k >> 10, c = k & 1023;
    o[idx] = w[(size_t)(c * 16 + hw) * 800 + n];
}
__global__ void perm_dec(const float* __restrict__ w, const float* __restrict__ b,
                         float* __restrict__ ow, float* __restrict__ ob) {
    long idx = (long)blockIdx.x * 256 + threadIdx.x;
    if (idx >= (long)800 * 9216) return;
    int k = (int)(idx / 9216), n = (int)(idx - (long)k * 9216);
    int hw = n >> 10, c = n & 1023;
    ow[idx] = w[(size_t)k * 9216 + c * 9 + hw];
    if (k == 0) ob[n] = b[c * 9 + hw];
}

__global__ void reduce_conv4(const float* __restrict__ part, const float* __restrict__ bias,
                             float* __restrict__ h4) {
    int idx = blockIdx.x * 256 + threadIdx.x;
    if (idx >= 1600 * 1024) return;
    int c = idx & 1023;
    float s = 0.f;
#pragma unroll
    for (int z = 0; z < 4; z++) s += part[(size_t)z * 1600 * 1024 + idx];
    s += bias[c];
    h4[idx] = (s >= 0.f) ? s : 0.01f * s;
}
__global__ void reduce_fc(const float* __restrict__ part, const float* __restrict__ bias,
                          float* __restrict__ out) {
    int idx = blockIdx.x * 256 + threadIdx.x;
    if (idx >= 80000) return;
    int n = idx % 800;
    float s = 0.f;
#pragma unroll
    for (int z = 0; z < 8; z++) s += part[(size_t)z * 80000 + idx];
    s += bias[n];
    out[idx] = fmaxf(s, 0.f);
}

__global__ void init_tab(float* tab) {
    int k = blockIdx.x * 256 + threadIdx.x;
    if (k < 800) tab[k] = (float)cos(2.0 * 3.141592653589793238462643 * (double)k / 800.0);
}
__global__ void compute_R(const float* __restrict__ eig, const float* __restrict__ tab,
                          float* __restrict__ R) {
    int b = blockIdx.x;
    __shared__ float s[800], t[800];
    for (int i = threadIdx.x; i < 800; i += 256) { s[i] = eig[b * 800 + i]; t[i] = tab[i]; }
    __syncthreads();
    for (int o = threadIdx.x; o < 800; o += 256) {
        int m = o >> 3, l = o & 7;
        float acc = 0.f;
        for (int q = 0; q < 800; q++) {
            int mp = q >> 3, lp = q & 7;
            int ph = (8 * m * mp + 100 * l * lp) % 800;
            acc += s[q] * t[ph];
        }
        R[b * 800 + o] = acc;
    }
}
__global__ void write_C(const float* __restrict__ R, float* __restrict__ C) {
    int b = blockIdx.y, i = blockIdx.x;
    __shared__ float r[800];
    const float inv = 0.035355339059327376f;
    for (int q = threadIdx.x; q < 800; q += 256) r[q] = R[b * 800 + q] * inv;
    __syncthreads();
    size_t base = ((size_t)b * 800 + i) * 800;
    for (int j = threadIdx.x; j < 800; j += 256)
        C[base + j] = r[(i - j + 800) % 800];
}

__global__ void ct5_nhwc(const float* __restrict__ t4, const float* __restrict__ w,
                         const float* __restrict__ bias, float* __restrict__ out) {
    __shared__ float ws[576];
    for (int i = threadIdx.x; i < 576; i += 128) {
        int tap = i >> 6, ci = i & 63;
        int ky = tap / 3, kx = tap % 3;
        ws[i] = w[ci * 9 + (2 - ky) * 3 + (2 - kx)];
    }
    __syncthreads();
    int b = blockIdx.y;
    int o = blockIdx.x * 128 + threadIdx.x;
    if (o >= 2401) return;
    int oy = o / 49, ox = o % 49;
    float acc = bias[0];
#pragma unroll
    for (int ky = 0; ky < 3; ky++) {
        int iy = oy + ky - 2;
        if ((unsigned)iy >= 47u) continue;
#pragma unroll
        for (int kx = 0; kx < 3; kx++) {
            int ix = ox + kx - 2;
            if ((unsigned)ix >= 47u) continue;
            const float4* p4 = (const float4*)(t4 + ((size_t)(b * 47 + iy) * 47 + ix) * 64);
            const float4* w4 = (const float4*)(ws + (ky * 3 + kx) * 64);
#pragma unroll
            for (int q = 0; q < 16; q++) {
                float4 v = p4[q], wv = w4[q];
                acc += v.x * wv.x + v.y * wv.y + v.z * wv.z + v.w * wv.w;
            }
        }
    }
    out[(size_t)b * 2401 + o] = acc;
}

// ---------------- host ----------------
static float* symaddr(const void* s) {
    void* p = nullptr; cudaGetSymbolAddress(&p, s); return (float*)p;
}
static int4 all4(int v) { return make_int4(v, v, v, v); }

static void run_bn_norm(float* h, int C, long total) {
    bn_zero_k<<<4, 256>>>();
    bn_part<<<1024, 256>>>(h, C, total);
    bn_fin<<<4, 256>>>(symaddr(g_mean), symaddr(g_invstd), C, (float)total / C);
    long nb = (total + 255) / 256;
    if (nb > 8192) nb = 8192;
    norm_k<<<(int)nb, 256>>>(h, symaddr(g_mean), symaddr(g_invstd), C, total);
}

struct PM { int4 Mz, Kz, wOff, HWpz, OWpz, pyz, pxz, ky0z, kx0z, nkxz; int maxM, maxKt; };
static PM pmeta(int B, int CI, int OH, int OW, int pd, int CO) {
    PM m{}; int Mv[4], Kv[4], wo[4], hwp[4], owp[4], pyv[4], pxv[4], k0v[4], kx0v[4], nkxv[4];
    int wacc = 0, i = 0; m.maxM = 0; m.maxKt = 0;
    for (int py = 0; py < 2; py++)
        for (int px = 0; px < 2; px++, i++) {
            int ky0 = ((pd - py) % 2 + 2) % 2, nky = 2 - ky0;
            int kx0 = ((pd - px) % 2 + 2) % 2, nkx = 2 - kx0;
            int OHp = (OH - py + 1) / 2, OWp = (OW - px + 1) / 2;
            int Kt = CI * nky * nkx, Mp = B * OHp * OWp;
            Mv[i] = Mp; Kv[i] = Kt; wo[i] = wacc;
            hwp[i] = OHp * OWp; owp[i] = OWp;
            pyv[i] = py; pxv[i] = px; k0v[i] = ky0; kx0v[i] = kx0; nkxv[i] = nkx;
            wacc += CO * Kt;
            if (Mp > m.maxM) m.maxM = Mp;
            if (Kt > m.maxKt) m.maxKt = Kt;
        }
    m.Mz = make_int4(Mv[0], Mv[1], Mv[2], Mv[3]);
    m.Kz = make_int4(Kv[0], Kv[1], Kv[2], Kv[3]);
    m.wOff = make_int4(wo[0], wo[1], wo[2], wo[3]);
    m.HWpz = make_int4(hwp[0], hwp[1], hwp[2], hwp[3]);
    m.OWpz = make_int4(owp[0], owp[1], owp[2], owp[3]);
    m.pyz = make_int4(pyv[0], pyv[1], pyv[2], pyv[3]);
    m.pxz = make_int4(pxv[0], pxv[1], pxv[2], pxv[3]);
    m.ky0z = make_int4(k0v[0], k0v[1], k0v[2], k0v[3]);
    m.kx0z = make_int4(kx0v[0], kx0v[1], kx0v[2], kx0v[3]);
    m.nkxz = make_int4(nkxv[0], nkxv[1], nkxv[2], nkxv[3]);
    return m;
}

static GP base_gp() { GP p{}; p.act = 0; return p; }

// fwd conv via implicit GEMM (input normalized NHWC)
static void conv_fwd(const float* in, const float* wraw, const float* bias, float* out,
                     int B, int CI, int CO, int IH, int OWo, int splitK) {
    float* wT = symaddr(g_wT);
    int K = 9 * CI;
    wt_fwd<<<(K * CO + 255) / 256, 256>>>(wraw, wT, CI, CO);
    GP p = base_gp();
    p.A = in; p.B = wT; p.bias = bias;
    p.N = CO; p.lda = 0; p.ldb = CO;
    p.CI = CI; p.IH = IH; p.IW = IH; p.OW = OWo; p.OHW = OWo * OWo; p.s = 2; p.pp = 1;
    p.M = B * p.OHW;
    if (splitK == 1) {
        p.C = out; p.K = K; p.act = 1;
        dim3 g((CO + 127) / 128, (p.M + 127) / 128, 1);
        gemm_u<128, 128, 8, 8, 1, 0><<<g, 256>>>(p);
    } else {
        p.C = symaddr(g_part); p.K = K / splitK; p.act = 0;
        dim3 g((CO + 127) / 128, (p.M + 127) / 128, splitK);
        gemm_u<128, 128, 8, 8, 1, 1><<<g, 256>>>(p);
    }
}

static void convT_layer(int variant, const float* in, const float* wraw, const float* bias,
                        float* out, int B, int CI, int CO, int IH, int OH, int pd) {
    float* wT = symaddr(g_wT);
    PM m = pmeta(B, CI, OH, OH, pd, CO);
    wt_par<<<dim3((m.maxKt * CO + 255) / 256, 1, 4), 256>>>(
        in == nullptr ? nullptr : wraw, wT, CI, CO, m.Kz, m.wOff, m.ky0z, m.kx0z, m.nkxz);
    GP p = base_gp();
    p.A = in; p.B = wT; p.bias = bias; p.C = out;
    p.N = CO; p.ldb = CO; p.CI = CI; p.IH = IH; p.IW = IH; p.pd = pd;
    p.Mz = m.Mz; p.Kz = m.Kz; p.wOffz = m.wOff; p.HWpz = m.HWpz; p.OWpz = m.OWpz;
    p.pyz = m.pyz; p.pxz = m.pxz; p.ky0z = m.ky0z; p.kx0z = m.kx0z; p.nkxz = m.nkxz;
    p.OHfull = OH; p.OWfull = OH; p.CO = CO; p.act = 0;
    if (variant == 1) {
        dim3 g((CO + 63) / 64, (m.maxM + 63) / 64, 4);
        gemm_u<64, 64, 4, 4, 2, 3><<<g, 256>>>(p);
    } else {
        dim3 g((CO + 63) / 64, (m.maxM + 127) / 128, 4);
        gemm_u<128, 64, 8, 4, 2, 3><<<g, 256>>>(p);
    }
}

extern "C" void kernel_launch(void* const* d_in, const int* in_sizes, int n_in,
                              void* d_out, int out_size) {
    const float* x       = (const float*)d_in[0];
    const float* conv1_w = (const float*)d_in[1];
    const float* conv1_b = (const float*)d_in[2];
    const float* conv2_w = (const float*)d_in[3];
    const float* conv2_b = (const float*)d_in[4];
    const float* conv3_w = (const float*)d_in[5];
    const float* conv3_b = (const float*)d_in[6];
    const float* conv4_w = (const float*)d_in[7];
    const float* conv4_b = (const float*)d_in[8];
    const float* fc_w    = (const float*)d_in[9];
    const float* fc_b    = (const float*)d_in[10];
    const float* dec_w   = (const float*)d_in[11];
    const float* dec_b   = (const float*)d_in[12];
    const float* ct1_w   = (const float*)d_in[13];
    const float* ct1_b   = (const float*)d_in[14];
    const float* ct2_w   = (const float*)d_in[15];
    const float* ct2_b   = (const float*)d_in[16];
    const float* ct3_w   = (const float*)d_in[17];
    const float* ct3_b   = (const float*)d_in[18];
    const float* ct4_w   = (const float*)d_in[19];
    const float* ct4_b   = (const float*)d_in[20];
    const float* ct5_w   = (const float*)d_in[21];
    const float* ct5_b   = (const float*)d_in[22];

    float* out = (float*)d_out;
    float* out_d   = out;
    float* out_C   = out + 240100;
    float* out_eig = out + 240100 + 64000000;

    float* h1 = symaddr(g_h1);
    float* h2 = symaddr(g_h2);
    float* h3 = symaddr(g_h3);
    float* h4 = symaddr(g_h4);
    float* part = symaddr(g_part);
    float* wT = symaddr(g_wT);
    float* R  = symaddr(g_R);
    float* tab = symaddr(g_tab);
    float* d0 = symaddr(g_d0);
    float* t1 = symaddr(g_t1);
    float* t2 = symaddr(g_t2);
    float* t3 = symaddr(g_t3);
    float* t4 = symaddr(g_t4);
    float* biasP = symaddr(g_bias);
    const int B = 100;

    // encoder (all NHWC)
    conv1_nhwc<<<dim3(1024, B), 128>>>(x, conv1_w, conv1_b, h1);
    run_bn_norm(h1, 128, (long)13107200);
    conv_fwd(h1, conv2_w, conv2_b, h2, B, 128, 256, 32, 16, 1);
    run_bn_norm(h2, 256, (long)6553600);
    conv_fwd(h2, conv3_w, conv3_b, h3, B, 256, 1024, 16, 8, 1);
    run_bn_norm(h3, 1024, (long)6553600);
    conv_fwd(h3, conv4_w, conv4_b, nullptr, B, 1024, 1024, 8, 4, 4);   // split-K=4 -> part
    reduce_conv4<<<(1600 * 1024 + 255) / 256, 256>>>(part, conv4_b, h4);
    run_bn_norm(h4, 1024, (long)1638400);

    // fc: A = h4 [100,16384] NHWC-flat, B = row-permuted fc_w, split-K=8
    perm_fc<<<(16384 * 800 + 255) / 256, 256>>>(fc_w, wT);
    {
        GP p = base_gp();
        p.A = h4; p.B = wT; p.bias = fc_b; p.C = part;
        p.M = 100; p.N = 800; p.K = 2048; p.lda = 16384; p.ldb = 800;
        dim3 g(13, 2, 8);
        gemm_u<64, 64, 4, 4, 0, 1><<<g, 256>>>(p);
    }
    reduce_fc<<<(80000 + 255) / 256, 256>>>(part, fc_b, out_eig);

    // spectral
    init_tab<<<4, 256>>>(tab);
    compute_R<<<B, 256>>>(out_eig, tab, R);
    write_C<<<dim3(800, B), 256>>>(R, out_C);

    // dec -> d0 NHWC (column-permuted dec_w + permuted bias)
    perm_dec<<<(int)(((long)800 * 9216 + 255) / 256), 256>>>(dec_w, dec_b, wT, biasP);
    {
        GP p = base_gp();
        p.A = R; p.B = wT; p.bias = biasP; p.C = d0;
        p.M = 100; p.N = 9216; p.K = 800; p.lda = 800; p.ldb = 9216; p.act = 0;
        dim3 g(144, 2, 1);
        gemm_u<64, 64, 4, 4, 0, 0><<<g, 256>>>(p);
    }

    // decoder convT (parity, implicit gather)
    convT_layer(1, d0, ct1_w, ct1_b, t1, B, 1024, 512, 3, 5, 1);
    convT_layer(1, t1, ct2_w, ct2_b, t2, B, 512, 256, 5, 11, 2);
    convT_layer(2, t2, ct3_w, ct3_b, t3, B, 256, 128, 11, 23, 2);
    convT_layer(2, t3, ct4_w, ct4_b, t4, B, 128, 64, 23, 47, 2);
    ct5_nhwc<<<dim3((2401 + 127) / 128, B), 128>>>(t4, ct5_w, ct5_b, out_d);
}